// round 8
// baseline (speedup 1.0000x reference)
#include <cuda_runtime.h>
#include <math.h>

#define Bb 32
#define Nn 1024
#define Ee 512
#define Ff 300
#define HH 300
#define Vv 50001

constexpr int ROWS  = Bb * Nn;   // 32768
constexpr int EROWS = Bb * Ee;   // 16384
constexpr int YW    = 304;       // y/edge row width (300 data + w/Z + pad)
constexpr int SSTG  = 128 * 36 + 32 * 72;      // floats per stage (A + B)
constexpr int SMEMB = SSTG * 4 * 4;            // 110592 B, 4 stages

// ---------------- scratch ----------------------------------------------------
__device__ float g_hidden[ROWS * Ff];
__device__ float g_px4   [ROWS * 600];   // [proj | x4] layer1
__device__ float g_xx    [ROWS * 600];   // [x4 | xW] layer2
__device__ float g_s1    [ROWS];
__device__ float g_sn    [ROWS];
__device__ float g_se    [EROWS];
__device__ float g_y     [ROWS * YW];
__device__ float g_edge  [EROWS * YW];
__device__ float g_e4    [EROWS * Ff];
__device__ float g_u2    [Bb * Nn * Ee];
__device__ float g_zpart [ROWS * 16];
__device__ float g_invZe [EROWS];
__device__ float g_invZn [ROWS];
__device__ float g_x1    [ROWS * Ff];
__device__ float g_sem   [ROWS * HH];
__device__ float g_comb  [ROWS * 2 * HH];
__device__ float g_hpre  [ROWS * HH];
__device__ float g_c     [2];
__device__ float g_s1max [Bb];
__device__ float g_snmax [Bb];
__device__ float g_semax [Bb];
__device__ float g_wt    [740000];   // prepped weights

// ---------------- tf32 helpers ----------------------------------------------
__device__ __forceinline__ unsigned to_tf32(float x) {
    unsigned r;
    asm("cvt.rna.tf32.f32 %0, %1;" : "=r"(r) : "f"(x));
    return r;
}
__device__ __forceinline__ float rtf(float x) { return __uint_as_float(to_tf32(x)); }

__device__ __forceinline__ void mma_tf32(float* d, const unsigned* a, const unsigned* b) {
    asm volatile(
        "mma.sync.aligned.m16n8k8.row.col.f32.tf32.tf32.f32 "
        "{%0,%1,%2,%3}, {%4,%5,%6,%7}, {%8,%9}, {%0,%1,%2,%3};"
        : "+f"(d[0]), "+f"(d[1]), "+f"(d[2]), "+f"(d[3])
        : "r"(a[0]), "r"(a[1]), "r"(a[2]), "r"(a[3]), "r"(b[0]), "r"(b[1]));
}

__device__ __forceinline__ void cp16(void* smem_dst, const void* gsrc, bool pred) {
    unsigned d = (unsigned)__cvta_generic_to_shared(smem_dst);
    int sz = pred ? 16 : 0;
    asm volatile("cp.async.ca.shared.global [%0], [%1], 16, %2;" :: "r"(d), "l"(gsrc), "r"(sz));
}

// ---------------- tensor-core GEMM, cp.async 4-stage -------------------------
// Inputs MUST be tf32-rounded. C = rowscale(A@B) (+bias) (ELU) (round) (invZe col).
template <bool TRANSB, int ACT, bool ROUND, bool WRZ>
__global__ void __launch_bounds__(128)
mma_gemm_k(const float* __restrict__ A, const float* __restrict__ B,
           const float* __restrict__ bias, const float* __restrict__ rowscale,
           float* __restrict__ C, float* __restrict__ zout,
           int M, int N, int K, int lda, int ldb, int ldc,
           long sA, long sB, long sC, long sScale)
{
    extern __shared__ float sm[];
    constexpr int BOFF = 128 * 36;

    A += (long)blockIdx.z * sA;
    B += (long)blockIdx.z * sB;
    C += (long)blockIdx.z * sC;
    const float* rs = rowscale ? rowscale + (long)blockIdx.z * sScale : nullptr;

    const int tid  = threadIdx.x;
    const int warp = tid >> 5, lane = tid & 31;
    const int g    = lane >> 2, tig = lane & 3;
    const int wm   = warp >> 1, wn = warp & 1;
    const int m0   = blockIdx.y * 128, n0 = blockIdx.x * 64;

    float acc[4][4][4];
#pragma unroll
    for (int i = 0; i < 4; ++i)
#pragma unroll
        for (int j = 0; j < 4; ++j)
#pragma unroll
            for (int l = 0; l < 4; ++l) acc[i][j][l] = 0.f;

    const int kt = (K + 31) / 32;

    auto issue = [&](int t, int st) {
        int k0 = t * 32;
        float* As = sm + st * SSTG;
        float* Bs = As + BOFF;
#pragma unroll
        for (int i = 0; i < 8; ++i) {          // A: 128x32
            int f = tid + i * 128;
            int row = f >> 3, c4 = (f & 7) * 4;
            int gm = m0 + row, gk = k0 + c4;
            bool p = (gm < M) && (gk < K);
            cp16(&As[row * 36 + c4], p ? (A + (long)gm * lda + gk) : A, p);
        }
#pragma unroll
        for (int i = 0; i < 4; ++i) {
            int f = tid + i * 128;
            if (TRANSB) {                       // BsT: [n=64][36]
                int nr = f >> 3, k4 = (f & 7) * 4;
                int gn = n0 + nr, gk = k0 + k4;
                bool p = (gn < N) && (gk < K);
                cp16(&Bs[nr * 36 + k4], p ? (B + (long)gn * ldb + gk) : B, p);
            } else {                            // Bs: [k=32][72]
                int row = f >> 4, c4 = (f & 15) * 4;
                int gk = k0 + row, gn = n0 + c4;
                bool p = (gk < K) && (gn < N);
                cp16(&Bs[row * 72 + c4], p ? (B + (long)gk * ldb + gn) : B, p);
            }
        }
        asm volatile("cp.async.commit_group;");
    };

    issue(0, 0);
    if (kt > 1) issue(1, 1);
    if (kt > 2) issue(2, 2);

    for (int t = 0; t < kt; ++t) {
        asm volatile("cp.async.wait_group 2;");
        __syncthreads();
        if (t + 3 < kt) issue(t + 3, (t + 3) & 3);

        const float* As = sm + (t & 3) * SSTG;
        const float* Bs = As + BOFF;
#pragma unroll
        for (int ks = 0; ks < 4; ++ks) {
            const int kb = ks * 8;
            unsigned af[4][4], bf[4][2];
#pragma unroll
            for (int mi = 0; mi < 4; ++mi) {
                int r = wm * 64 + mi * 16 + g;
                af[mi][0] = __float_as_uint(As[(r    ) * 36 + kb + tig]);
                af[mi][1] = __float_as_uint(As[(r + 8) * 36 + kb + tig]);
                af[mi][2] = __float_as_uint(As[(r    ) * 36 + kb + tig + 4]);
                af[mi][3] = __float_as_uint(As[(r + 8) * 36 + kb + tig + 4]);
            }
#pragma unroll
            for (int ni = 0; ni < 4; ++ni) {
                int c = wn * 32 + ni * 8 + g;
                if (TRANSB) {
                    bf[ni][0] = __float_as_uint(Bs[c * 36 + kb + tig]);
                    bf[ni][1] = __float_as_uint(Bs[c * 36 + kb + tig + 4]);
                } else {
                    bf[ni][0] = __float_as_uint(Bs[(kb + tig    ) * 72 + c]);
                    bf[ni][1] = __float_as_uint(Bs[(kb + tig + 4) * 72 + c]);
                }
            }
#pragma unroll
            for (int mi = 0; mi < 4; ++mi)
#pragma unroll
                for (int ni = 0; ni < 4; ++ni)
                    mma_tf32(acc[mi][ni], af[mi], bf[ni]);
        }
        __syncthreads();
    }

#pragma unroll
    for (int mi = 0; mi < 4; ++mi) {
#pragma unroll
        for (int ni = 0; ni < 4; ++ni) {
            int r = m0 + wm * 64 + mi * 16 + g;
            int c = n0 + wn * 32 + ni * 8 + tig * 2;
            if (c >= N) continue;
            float bx = bias ? bias[c] : 0.f;
            float by = bias ? bias[c + 1] : 0.f;
#pragma unroll
            for (int h = 0; h < 2; ++h) {
                int rr = r + h * 8;
                if (rr >= M) continue;
                float sc = rs ? rs[rr] : 1.f;
                float vx = acc[mi][ni][h * 2 + 0] * sc + bx;
                float vy = acc[mi][ni][h * 2 + 1] * sc + by;
                if (ACT == 1) {
                    vx = (vx > 0.f) ? vx : expm1f(vx);
                    vy = (vy > 0.f) ? vy : expm1f(vy);
                }
                if (WRZ && c == Ff)
                    zout[(long)blockIdx.z * Ee + rr] = (vx > 0.f) ? 1.f / vx : 0.f;
                if (ROUND) { vx = rtf(vx); vy = rtf(vy); }
                *(float2*)(C + (long)rr * ldc + c) = make_float2(vx, vy);
            }
        }
    }
}

// ---------------- prep kernels -----------------------------------------------
__global__ void cvt_k(const float* __restrict__ src, float* __restrict__ dst, int n4)
{
    int i = blockIdx.x * 256 + threadIdx.x;
    if (i < n4) {
        float4 v = ((const float4*)src)[i];
        v.x = rtf(v.x); v.y = rtf(v.y); v.z = rtf(v.z); v.w = rtf(v.w);
        ((float4*)dst)[i] = v;
    }
}

// Wcat[k][j] = j<300 ? L[j][k] (transposed) : R[k][j-300]
__global__ void prep_cat_k(const float* __restrict__ L, const float* __restrict__ R,
                           float* __restrict__ Wcat, bool transL)
{
    int i = blockIdx.x * 256 + threadIdx.x;
    if (i >= 300 * 600) return;
    int k = i / 600, j = i % 600;
    float v = (j < 300) ? (transL ? L[j * 300 + k] : L[k * 300 + j])
                        : R[k * 300 + (j - 300)];
    Wcat[i] = rtf(v);
}

__global__ void prep_bias_k(const float* __restrict__ bp, float* __restrict__ b600)
{
    int i = blockIdx.x * 256 + threadIdx.x;
    if (i < 600) b600[i] = (i < 300) ? bp[i] : 0.f;
}

__global__ void gather_k(const int* __restrict__ idx,
                         const float* __restrict__ emb, float* __restrict__ out)
{
    int row = blockIdx.x;
    int id = idx[row];
    id = max(0, min(id, Vv - 1));
    const float4* src = (const float4*)(emb + (long)id * Ff);
    float4* dst = (float4*)(out + (long)row * Ff);
    int c = threadIdx.x;
    if (c < Ff / 4) {
        float4 v = src[c];
        v.x = rtf(v.x); v.y = rtf(v.y); v.z = rtf(v.z); v.w = rtf(v.w);
        dst[c] = v;
    }
}

__global__ void dot_scalar_k(const float* __restrict__ a, const float* __restrict__ b,
                             float* __restrict__ out, int K)
{
    __shared__ float sh[128];
    float s = 0.f;
    for (int c = threadIdx.x; c < K; c += 128) s += a[c] * b[c];
    sh[threadIdx.x] = s; __syncthreads();
    for (int o = 64; o > 0; o >>= 1) {
        if (threadIdx.x < o) sh[threadIdx.x] += sh[threadIdx.x + o];
        __syncthreads();
    }
    if (threadIdx.x == 0) *out = sh[0];
}

__global__ void rowdots_k(const float* __restrict__ X, int ldx,
                          const float* __restrict__ v1, const float* __restrict__ v2,
                          const float* __restrict__ cptr, float alpha,
                          float* __restrict__ o1, float* __restrict__ o2, int K)
{
    int row = blockIdx.x;
    const float* x = X + (long)row * ldx;
    float s1 = 0.f, s2 = 0.f;
    for (int c = threadIdx.x; c < K; c += 128) {
        float xv = x[c];
        s1 += xv * v1[c];
        s2 += xv * v2[c];
    }
    __shared__ float r1[128], r2[128];
    r1[threadIdx.x] = s1; r2[threadIdx.x] = s2; __syncthreads();
    for (int o = 64; o > 0; o >>= 1) {
        if (threadIdx.x < o) { r1[threadIdx.x] += r1[threadIdx.x + o]; r2[threadIdx.x] += r2[threadIdx.x + o]; }
        __syncthreads();
    }
    if (threadIdx.x == 0) {
        float t = *cptr + r1[0];
        o1[row] = (t >= 0.f) ? t : alpha * t;
        o2[row] = r2[0];
    }
}

__global__ void rowdot_k(const float* __restrict__ X, const float* __restrict__ v,
                         float* __restrict__ o, int K)
{
    int row = blockIdx.x;
    const float* x = X + (long)row * K;
    float s = 0.f;
    for (int c = threadIdx.x; c < K; c += 128) s += x[c] * v[c];
    __shared__ float sh[128];
    sh[threadIdx.x] = s; __syncthreads();
    for (int o2 = 64; o2 > 0; o2 >>= 1) {
        if (threadIdx.x < o2) sh[threadIdx.x] += sh[threadIdx.x + o2];
        __syncthreads();
    }
    if (threadIdx.x == 0) o[row] = sh[0];
}

// two per-batch maxes in one pass
__global__ void bmax2_k(const float* __restrict__ X, const float* __restrict__ Y,
                        float* __restrict__ ox, float* __restrict__ oy, int len)
{
    __shared__ float shx[256], shy[256];
    int b = blockIdx.x;
    const float* x = X + (long)b * len;
    const float* y = Y + (long)b * len;
    float mx = -3.0e38f, my = -3.0e38f;
    for (int i = threadIdx.x; i < len; i += 256) {
        mx = fmaxf(mx, x[i]);
        my = fmaxf(my, y[i]);
    }
    shx[threadIdx.x] = mx; shy[threadIdx.x] = my; __syncthreads();
    for (int o = 128; o > 0; o >>= 1) {
        if (threadIdx.x < o) {
            shx[threadIdx.x] = fmaxf(shx[threadIdx.x], shx[threadIdx.x + o]);
            shy[threadIdx.x] = fmaxf(shy[threadIdx.x], shy[threadIdx.x + o]);
        }
        __syncthreads();
    }
    if (threadIdx.x == 0) { ox[b] = shx[0]; oy[b] = shy[0]; }
}

__global__ void bmax_k(const float* __restrict__ X, float* __restrict__ out, int len)
{
    __shared__ float sh[256];
    int b = blockIdx.x;
    const float* x = X + (long)b * len;
    float m = -3.0e38f;
    for (int i = threadIdx.x; i < len; i += 256) m = fmaxf(m, x[i]);
    sh[threadIdx.x] = m; __syncthreads();
    for (int o = 128; o > 0; o >>= 1) {
        if (threadIdx.x < o) sh[threadIdx.x] = fmaxf(sh[threadIdx.x], sh[threadIdx.x + o]);
        __syncthreads();
    }
    if (threadIdx.x == 0) out[b] = sh[0];
}

__global__ void build_y_k(const float* __restrict__ X, int ldx,
                          const float* __restrict__ s1, const float* __restrict__ s1max,
                          float* __restrict__ y)
{
    int row = blockIdx.x;
    int b = row >> 10;
    float w = expf(s1[row] - s1max[b]);
    const float* x = X + (long)row * ldx;
    float* yy = y + (long)row * YW;
    for (int c = threadIdx.x; c < YW; c += 128)
        yy[c] = (c < Ff) ? rtf(w * x[c]) : ((c == Ff) ? rtf(w) : 0.f);
}

__global__ void attn_build_k(const float* __restrict__ HT, const float* __restrict__ sn,
                             const float* __restrict__ se, const float* __restrict__ snmax,
                             const float* __restrict__ semax, const float* __restrict__ invZe,
                             float* __restrict__ u2, float* __restrict__ zpart, float alpha)
{
    __shared__ float t[32][33];
    int b  = blockIdx.z;
    int n0 = blockIdx.x * 32, e0 = blockIdx.y * 32;
    int tx = threadIdx.x, ty = threadIdx.y;   // (32,8)

    float sh = snmax[b] + semax[b];
    sh = (sh >= 0.f) ? sh : alpha * sh;

    const float* src = HT + (long)b * Ee * Nn;
    float snv = sn[(long)b * Nn + n0 + tx];
#pragma unroll
    for (int i = 0; i < 32; i += 8) {
        int e = e0 + ty + i;
        float sev = se[(long)b * Ee + e];
        float ht  = src[(long)e * Nn + n0 + tx];
        float v = snv + sev;
        v = (v >= 0.f) ? v : alpha * v;
        t[ty + i][tx] = (ht > 0.f) ? expf(v - sh) : 0.f;
    }
    __syncthreads();

    float iz = invZe[(long)b * Ee + e0 + tx];
    float* dst = u2 + (long)b * Nn * Ee;
#pragma unroll
    for (int i = 0; i < 32; i += 8) {
        int n = n0 + ty + i;
        dst[(long)n * Ee + e0 + tx] = rtf(t[tx][ty + i] * iz);
    }

    if (ty == 0) {
        float s = 0.f;
#pragma unroll
        for (int e = 0; e < 32; ++e) s += t[e][tx];
        zpart[((long)b * Nn + n0 + tx) * 16 + blockIdx.y] = s;
    }
}

__global__ void zsum_k(const float* __restrict__ zpart, float* __restrict__ invZn)
{
    int i = blockIdx.x * 256 + threadIdx.x;
    if (i < ROWS) {
        float s = 0.f;
#pragma unroll
        for (int j = 0; j < 16; ++j) s += zpart[(long)i * 16 + j];
        invZn[i] = (s > 0.f) ? 1.f / s : 0.f;
    }
}

__global__ void concat_k(const float* __restrict__ px4, const float* __restrict__ sem,
                         float* __restrict__ comb)
{
    int row = blockIdx.x;
    float* dst = comb + (long)row * (2 * HH);
    const float* p = px4 + (long)row * 600;
    const float* s = sem + (long)row * HH;
    for (int c = threadIdx.x; c < HH; c += 128) {
        dst[c]      = rtf(p[c]);
        dst[HH + c] = rtf(s[c]);
    }
}

__global__ void final_k(const float* __restrict__ hpre, const float* __restrict__ px4,
                        const float* __restrict__ sem, const float* __restrict__ ln_g,
                        const float* __restrict__ ln_b, const float* __restrict__ A2,
                        const float* __restrict__ b2, float* __restrict__ out)
{
    int row = blockIdx.x;
    int tid = threadIdx.x;
    __shared__ float hs[HH];
    __shared__ float red[128];
    const float* hp = hpre + (long)row * HH;

    float s = 0.f;
    for (int c = tid; c < HH; c += 128) {
        float t = tanhf(hp[c]);
        hs[c] = t;
        s += t;
    }
    red[tid] = s; __syncthreads();
    for (int o = 64; o > 0; o >>= 1) {
        if (tid < o) red[tid] += red[tid + o];
        __syncthreads();
    }
    float mean = red[0] / (float)HH;
    __syncthreads();

    float vs = 0.f;
    for (int c = tid; c < HH; c += 128) { float d = hs[c] - mean; vs += d * d; }
    red[tid] = vs; __syncthreads();
    for (int o = 64; o > 0; o >>= 1) {
        if (tid < o) red[tid] += red[tid + o];
        __syncthreads();
    }
    float rstd = rsqrtf(red[0] / (float)HH + 1e-5f);
    __syncthreads();

    float gdot = 0.f;
    for (int c = tid; c < HH; c += 128) {
        float hn = (hs[c] - mean) * rstd * ln_g[c] + ln_b[c];
        gdot += hn * A2[c];
    }
    red[tid] = gdot; __syncthreads();
    for (int o = 64; o > 0; o >>= 1) {
        if (tid < o) red[tid] += red[tid + o];
        __syncthreads();
    }
    float gate = 1.f / (1.f + expf(-(red[0] + b2[0])));
    __syncthreads();

    const float* p = px4 + (long)row * 600;
    const float* se = sem + (long)row * HH;
    float* o = out + (long)row * HH;
    for (int c = tid; c < HH; c += 128)
        o[c] = gate * se[c] + (1.f - gate) * p[c];
}

// ---------------- launcher ---------------------------------------------------
extern "C" void kernel_launch(void* const* d_in, const int* in_sizes, int n_in,
                              void* d_out, int out_size)
{
    const int*   inp  = (const int*)d_in[0];
    const float* HT   = (const float*)d_in[1];
    const float* emb  = (const float*)d_in[2];
    const float* Wp   = (const float*)d_in[3];
    const float* bp   = (const float*)d_in[4];
    const float* w2_1 = (const float*)d_in[5];
    const float* w3_1 = (const float*)d_in[6];
    const float* wc1  = (const float*)d_in[7];
    const float* a11  = (const float*)d_in[8];
    const float* a21  = (const float*)d_in[9];
    const float* W2t  = (const float*)d_in[10];
    const float* w2_2 = (const float*)d_in[11];
    const float* w3_2 = (const float*)d_in[12];
    const float* wc2  = (const float*)d_in[13];
    const float* a12  = (const float*)d_in[14];
    const float* a22  = (const float*)d_in[15];
    const float* A1   = (const float*)d_in[16];
    const float* b1   = (const float*)d_in[17];
    const float* ln_g = (const float*)d_in[18];
    const float* ln_b = (const float*)d_in[19];
    const float* A2   = (const float*)d_in[20];
    const float* b2   = (const float*)d_in[21];
    float* outp = (float*)d_out;

    static bool attr_done = false;
    if (!attr_done) {
        cudaFuncSetAttribute((const void*)mma_gemm_k<false, 0, false, false>,
                             cudaFuncAttributeMaxDynamicSharedMemorySize, SMEMB);
        cudaFuncSetAttribute((const void*)mma_gemm_k<false, 0, true, true>,
                             cudaFuncAttributeMaxDynamicSharedMemorySize, SMEMB);
        cudaFuncSetAttribute((const void*)mma_gemm_k<false, 1, true, false>,
                             cudaFuncAttributeMaxDynamicSharedMemorySize, SMEMB);
        cudaFuncSetAttribute((const void*)mma_gemm_k<true, 0, false, false>,
                             cudaFuncAttributeMaxDynamicSharedMemorySize, SMEMB);
        attr_done = true;
    }

    float *hidden, *px4, *xx, *s1, *sn, *se, *y, *edge, *e4, *u2, *zpart,
          *invZe, *invZn, *x1, *sem, *comb, *hpre, *gc, *s1max, *snmax, *semax, *wt;
    cudaGetSymbolAddress((void**)&hidden, g_hidden);
    cudaGetSymbolAddress((void**)&px4,    g_px4);
    cudaGetSymbolAddress((void**)&xx,     g_xx);
    cudaGetSymbolAddress((void**)&s1,     g_s1);
    cudaGetSymbolAddress((void**)&sn,     g_sn);
    cudaGetSymbolAddress((void**)&se,     g_se);
    cudaGetSymbolAddress((void**)&y,      g_y);
    cudaGetSymbolAddress((void**)&edge,   g_edge);
    cudaGetSymbolAddress((void**)&e4,     g_e4);
    cudaGetSymbolAddress((void**)&u2,     g_u2);
    cudaGetSymbolAddress((void**)&zpart,  g_zpart);
    cudaGetSymbolAddress((void**)&invZe,  g_invZe);
    cudaGetSymbolAddress((void**)&invZn,  g_invZn);
    cudaGetSymbolAddress((void**)&x1,     g_x1);
    cudaGetSymbolAddress((void**)&sem,    g_sem);
    cudaGetSymbolAddress((void**)&comb,   g_comb);
    cudaGetSymbolAddress((void**)&hpre,   g_hpre);
    cudaGetSymbolAddress((void**)&gc,     g_c);
    cudaGetSymbolAddress((void**)&s1max,  g_s1max);
    cudaGetSymbolAddress((void**)&snmax,  g_snmax);
    cudaGetSymbolAddress((void**)&semax,  g_semax);
    cudaGetSymbolAddress((void**)&wt,     g_wt);

    float* Wcat1 = wt;                 // 180000
    float* Wcat2 = wt + 180000;        // 180000
    float* w31c  = wt + 360000;        // 90000
    float* w32c  = wt + 450000;        // 90000
    float* A1c   = wt + 540000;        // 180000
    float* b600  = wt + 720000;        // 600

    auto grid = [](int M, int N, int Z) {
        return dim3((N + 63) / 64, (M + 127) / 128, Z);
    };

    // ---- prep (idempotent) ----
    prep_cat_k<<<(180000 + 255) / 256, 256>>>(Wp,   w2_1, Wcat1, true);
    prep_cat_k<<<(180000 + 255) / 256, 256>>>(w2_2, W2t,  Wcat2, false);
    prep_bias_k<<<3, 256>>>(bp, b600);
    cvt_k<<<(22500 + 255) / 256, 256>>>(w3_1, w31c, 22500);
    cvt_k<<<(22500 + 255) / 256, 256>>>(w3_2, w32c, 22500);
    cvt_k<<<(45000 + 255) / 256, 256>>>(A1,   A1c,  45000);
    dot_scalar_k<<<1, 128>>>(wc1, a11, gc + 0, Ff);
    dot_scalar_k<<<1, 128>>>(wc2, a12, gc + 1, HH);
    gather_k<<<ROWS, 128>>>(inp, emb, hidden);

    // ---- fused [proj | x4] = hidden @ Wcat1 + b600 ----
    mma_gemm_k<false, 0, false, false><<<grid(ROWS, 600, 1), 128, SMEMB>>>(
        hidden, Wcat1, b600, nullptr, px4, nullptr, ROWS, 600, Ff, Ff, 600, 600, 0, 0, 0, 0);

    // ================= layer 1 (alpha 0.1, ELU) ==============================
    rowdots_k<<<ROWS, 128>>>(px4 + 300, 600, a11 + Ff, a21, gc + 0, 0.1f, s1, sn, Ff);
    bmax2_k<<<Bb, 256>>>(s1, sn, s1max, snmax, Nn);
    build_y_k<<<ROWS, 128>>>(hidden, Ff, s1, s1max, y);
    mma_gemm_k<false, 0, true, true><<<grid(Ee, YW, Bb), 128, SMEMB>>>(
        HT, y, nullptr, nullptr, edge, invZe, Ee, YW, Nn, Nn, YW, YW,
        (long)Ee * Nn, (long)Nn * YW, (long)Ee * YW, 0);
    mma_gemm_k<false, 0, false, false><<<grid(EROWS, Ff, 1), 128, SMEMB>>>(
        edge, w31c, nullptr, invZe, e4, nullptr, EROWS, Ff, Ff, YW, Ff, Ff, 0, 0, 0, 0);
    rowdot_k<<<EROWS, 128>>>(e4, a21 + Ff, se, Ff);
    bmax_k<<<Bb, 256>>>(se, semax, Ee);
    attn_build_k<<<dim3(Nn / 32, Ee / 32, Bb), dim3(32, 8)>>>(
        HT, sn, se, snmax, semax, invZe, u2, zpart, 0.1f);
    zsum_k<<<(ROWS + 255) / 256, 256>>>(zpart, invZn);
    mma_gemm_k<false, 1, true, false><<<grid(Nn, Ff, Bb), 128, SMEMB>>>(
        u2, edge, nullptr, invZn, x1, nullptr, Nn, Ff, Ee, Ee, YW, Ff,
        (long)Nn * Ee, (long)Ee * YW, (long)Nn * Ff, Nn);

    // ================= layer 2 (alpha 0.2, transfer) =========================
    mma_gemm_k<false, 0, false, false><<<grid(ROWS, 600, 1), 128, SMEMB>>>(
        x1, Wcat2, nullptr, nullptr, xx, nullptr, ROWS, 600, Ff, Ff, 600, 600, 0, 0, 0, 0);
    rowdots_k<<<ROWS, 128>>>(xx, 600, a12 + HH, a22, gc + 1, 0.2f, s1, sn, HH);
    bmax2_k<<<Bb, 256>>>(s1, sn, s1max, snmax, Nn);
    build_y_k<<<ROWS, 128>>>(xx + 300, 600, s1, s1max, y);
    mma_gemm_k<false, 0, true, true><<<grid(Ee, YW, Bb), 128, SMEMB>>>(
        HT, y, nullptr, nullptr, edge, invZe, Ee, YW, Nn, Nn, YW, YW,
        (long)Ee * Nn, (long)Nn * YW, (long)Ee * YW, 0);
    mma_gemm_k<false, 0, false, false><<<grid(EROWS, HH, 1), 128, SMEMB>>>(
        edge, w32c, nullptr, invZe, e4, nullptr, EROWS, HH, HH, YW, HH, HH, 0, 0, 0, 0);
    rowdot_k<<<EROWS, 128>>>(e4, a22 + HH, se, HH);
    bmax_k<<<Bb, 256>>>(se, semax, Ee);
    attn_build_k<<<dim3(Nn / 32, Ee / 32, Bb), dim3(32, 8)>>>(
        HT, sn, se, snmax, semax, invZe, u2, zpart, 0.2f);
    zsum_k<<<(ROWS + 255) / 256, 256>>>(zpart, invZn);
    mma_gemm_k<false, 0, false, false><<<grid(Nn, HH, Bb), 128, SMEMB>>>(
        u2, edge, nullptr, invZn, sem, nullptr, Nn, HH, Ee, Ee, YW, HH,
        (long)Nn * Ee, (long)Ee * YW, (long)Nn * HH, Nn);

    // ================= head ==================================================
    concat_k<<<ROWS, 128>>>(px4, sem, comb);
    mma_gemm_k<true, 0, false, false><<<grid(ROWS, HH, 1), 128, SMEMB>>>(
        comb, A1c, b1, nullptr, hpre, nullptr, ROWS, HH, 2 * HH, 2 * HH, 2 * HH, HH, 0, 0, 0, 0);
    final_k<<<ROWS, 128>>>(hpre, px4, sem, ln_g, ln_b, A2, b2, outp);
}

// round 9
// speedup vs baseline: 1.2073x; 1.2073x over previous
#include <cuda_runtime.h>
#include <math.h>

#define Bb 32
#define Nn 1024
#define Ee 512
#define Ff 300
#define HH 300
#define Vv 50001

constexpr int ROWS  = Bb * Nn;   // 32768
constexpr int EROWS = Bb * Ee;   // 16384
constexpr int YW    = 304;       // y/edge row width (300 data + w/Z + pad)
constexpr int SSTG  = 128 * 36 + 32 * 72;      // floats per stage (A + B)
constexpr int SMEMB = SSTG * 3 * 4;            // 82944 B, 3 stages (2 blocks/SM)

// ---------------- scratch ----------------------------------------------------
__device__ float g_hidden[ROWS * Ff];
__device__ float g_px4   [ROWS * 600];   // [proj | x4] layer1
__device__ float g_xx    [ROWS * 600];   // [x4 | xW] layer2
__device__ float g_s1    [ROWS];
__device__ float g_sn    [ROWS];
__device__ float g_se    [EROWS];
__device__ float g_y     [ROWS * YW];
__device__ float g_edge  [EROWS * YW];
__device__ float g_e4    [EROWS * Ff];
__device__ float g_u2    [Bb * Nn * Ee];
__device__ float g_zpart [ROWS * 16];
__device__ float g_invZe [EROWS];
__device__ float g_invZn [ROWS];
__device__ float g_x1    [ROWS * Ff];
__device__ float g_sem   [ROWS * HH];
__device__ float g_comb  [ROWS * 2 * HH];
__device__ float g_hpre  [ROWS * HH];
__device__ float g_c     [2];
__device__ float g_s1max [Bb];
__device__ float g_snmax [Bb];
__device__ float g_semax [Bb];
__device__ float g_wt    [740000];   // prepped weights

// ---------------- tf32 helpers ----------------------------------------------
__device__ __forceinline__ unsigned to_tf32(float x) {
    unsigned r;
    asm("cvt.rna.tf32.f32 %0, %1;" : "=r"(r) : "f"(x));
    return r;
}
__device__ __forceinline__ float rtf(float x) { return __uint_as_float(to_tf32(x)); }

__device__ __forceinline__ void mma_tf32(float* d, const unsigned* a, const unsigned* b) {
    asm volatile(
        "mma.sync.aligned.m16n8k8.row.col.f32.tf32.tf32.f32 "
        "{%0,%1,%2,%3}, {%4,%5,%6,%7}, {%8,%9}, {%0,%1,%2,%3};"
        : "+f"(d[0]), "+f"(d[1]), "+f"(d[2]), "+f"(d[3])
        : "r"(a[0]), "r"(a[1]), "r"(a[2]), "r"(a[3]), "r"(b[0]), "r"(b[1]));
}

__device__ __forceinline__ void cp16(void* smem_dst, const void* gsrc, bool pred) {
    unsigned d = (unsigned)__cvta_generic_to_shared(smem_dst);
    int sz = pred ? 16 : 0;
    asm volatile("cp.async.ca.shared.global [%0], [%1], 16, %2;" :: "r"(d), "l"(gsrc), "r"(sz));
}

// ---------------- tensor-core GEMM, cp.async 3-stage -------------------------
// Inputs MUST be tf32-rounded. C = rowscale(A@B) (+bias) (ELU) (round) (invZe col).
template <bool TRANSB, int ACT, bool ROUND, bool WRZ>
__global__ void __launch_bounds__(128)
mma_gemm_k(const float* __restrict__ A, const float* __restrict__ B,
           const float* __restrict__ bias, const float* __restrict__ rowscale,
           float* __restrict__ C, float* __restrict__ zout,
           int M, int N, int K, int lda, int ldb, int ldc,
           long sA, long sB, long sC, long sScale)
{
    extern __shared__ float sm[];
    constexpr int BOFF = 128 * 36;

    A += (long)blockIdx.z * sA;
    B += (long)blockIdx.z * sB;
    C += (long)blockIdx.z * sC;
    const float* rs = rowscale ? rowscale + (long)blockIdx.z * sScale : nullptr;

    const int tid  = threadIdx.x;
    const int warp = tid >> 5, lane = tid & 31;
    const int g    = lane >> 2, tig = lane & 3;
    const int wm   = warp >> 1, wn = warp & 1;
    const int m0   = blockIdx.y * 128, n0 = blockIdx.x * 64;

    float acc[4][4][4];
#pragma unroll
    for (int i = 0; i < 4; ++i)
#pragma unroll
        for (int j = 0; j < 4; ++j)
#pragma unroll
            for (int l = 0; l < 4; ++l) acc[i][j][l] = 0.f;

    const int kt = (K + 31) / 32;

    auto issue = [&](int t, int st) {
        int k0 = t * 32;
        float* As = sm + st * SSTG;
        float* Bs = As + BOFF;
#pragma unroll
        for (int i = 0; i < 8; ++i) {          // A: 128x32
            int f = tid + i * 128;
            int row = f >> 3, c4 = (f & 7) * 4;
            int gm = m0 + row, gk = k0 + c4;
            bool p = (gm < M) && (gk < K);
            cp16(&As[row * 36 + c4], p ? (A + (long)gm * lda + gk) : A, p);
        }
#pragma unroll
        for (int i = 0; i < 4; ++i) {
            int f = tid + i * 128;
            if (TRANSB) {                       // BsT: [n=64][36]
                int nr = f >> 3, k4 = (f & 7) * 4;
                int gn = n0 + nr, gk = k0 + k4;
                bool p = (gn < N) && (gk < K);
                cp16(&Bs[nr * 36 + k4], p ? (B + (long)gn * ldb + gk) : B, p);
            } else {                            // Bs: [k=32][72]
                int row = f >> 4, c4 = (f & 15) * 4;
                int gk = k0 + row, gn = n0 + c4;
                bool p = (gk < K) && (gn < N);
                cp16(&Bs[row * 72 + c4], p ? (B + (long)gk * ldb + gn) : B, p);
            }
        }
        asm volatile("cp.async.commit_group;");
    };

    issue(0, 0);
    if (kt > 1) issue(1, 1);

    for (int t = 0; t < kt; ++t) {
        asm volatile("cp.async.wait_group 1;");
        __syncthreads();
        if (t + 2 < kt) issue(t + 2, (t + 2) % 3);

        const float* As = sm + (t % 3) * SSTG;
        const float* Bs = As + BOFF;
#pragma unroll
        for (int ks = 0; ks < 4; ++ks) {
            const int kb = ks * 8;
            unsigned af[4][4], bf[4][2];
#pragma unroll
            for (int mi = 0; mi < 4; ++mi) {
                int r = wm * 64 + mi * 16 + g;
                af[mi][0] = __float_as_uint(As[(r    ) * 36 + kb + tig]);
                af[mi][1] = __float_as_uint(As[(r + 8) * 36 + kb + tig]);
                af[mi][2] = __float_as_uint(As[(r    ) * 36 + kb + tig + 4]);
                af[mi][3] = __float_as_uint(As[(r + 8) * 36 + kb + tig + 4]);
            }
#pragma unroll
            for (int ni = 0; ni < 4; ++ni) {
                int c = wn * 32 + ni * 8 + g;
                if (TRANSB) {
                    bf[ni][0] = __float_as_uint(Bs[c * 36 + kb + tig]);
                    bf[ni][1] = __float_as_uint(Bs[c * 36 + kb + tig + 4]);
                } else {
                    bf[ni][0] = __float_as_uint(Bs[(kb + tig    ) * 72 + c]);
                    bf[ni][1] = __float_as_uint(Bs[(kb + tig + 4) * 72 + c]);
                }
            }
#pragma unroll
            for (int mi = 0; mi < 4; ++mi)
#pragma unroll
                for (int ni = 0; ni < 4; ++ni)
                    mma_tf32(acc[mi][ni], af[mi], bf[ni]);
        }
        __syncthreads();
    }

#pragma unroll
    for (int mi = 0; mi < 4; ++mi) {
#pragma unroll
        for (int ni = 0; ni < 4; ++ni) {
            int r = m0 + wm * 64 + mi * 16 + g;
            int c = n0 + wn * 32 + ni * 8 + tig * 2;
            if (c >= N) continue;
            float bx = bias ? bias[c] : 0.f;
            float by = bias ? bias[c + 1] : 0.f;
#pragma unroll
            for (int h = 0; h < 2; ++h) {
                int rr = r + h * 8;
                if (rr >= M) continue;
                float sc = rs ? rs[rr] : 1.f;
                float vx = acc[mi][ni][h * 2 + 0] * sc + bx;
                float vy = acc[mi][ni][h * 2 + 1] * sc + by;
                if (ACT == 1) {
                    vx = (vx > 0.f) ? vx : expm1f(vx);
                    vy = (vy > 0.f) ? vy : expm1f(vy);
                }
                if (WRZ && c == Ff)
                    zout[(long)blockIdx.z * Ee + rr] = (vx > 0.f) ? 1.f / vx : 0.f;
                if (ROUND) { vx = rtf(vx); vy = rtf(vy); }
                *(float2*)(C + (long)rr * ldc + c) = make_float2(vx, vy);
            }
        }
    }
}

// ---------------- prep kernels -----------------------------------------------
__global__ void cvt_k(const float* __restrict__ src, float* __restrict__ dst, int n4)
{
    int i = blockIdx.x * 256 + threadIdx.x;
    if (i < n4) {
        float4 v = ((const float4*)src)[i];
        v.x = rtf(v.x); v.y = rtf(v.y); v.z = rtf(v.z); v.w = rtf(v.w);
        ((float4*)dst)[i] = v;
    }
}

// Wcat[k][j] = j<300 ? L[j][k] (transposed) : R[k][j-300]
__global__ void prep_cat_k(const float* __restrict__ L, const float* __restrict__ R,
                           float* __restrict__ Wcat, bool transL)
{
    int i = blockIdx.x * 256 + threadIdx.x;
    if (i >= 300 * 600) return;
    int k = i / 600, j = i % 600;
    float v = (j < 300) ? (transL ? L[j * 300 + k] : L[k * 300 + j])
                        : R[k * 300 + (j - 300)];
    Wcat[i] = rtf(v);
}

__global__ void prep_bias_k(const float* __restrict__ bp, float* __restrict__ b600)
{
    int i = blockIdx.x * 256 + threadIdx.x;
    if (i < 600) b600[i] = (i < 300) ? bp[i] : 0.f;
}

__global__ void gather_k(const int* __restrict__ idx,
                         const float* __restrict__ emb, float* __restrict__ out)
{
    int row = blockIdx.x;
    int id = idx[row];
    id = max(0, min(id, Vv - 1));
    const float4* src = (const float4*)(emb + (long)id * Ff);
    float4* dst = (float4*)(out + (long)row * Ff);
    int c = threadIdx.x;
    if (c < Ff / 4) {
        float4 v = src[c];
        v.x = rtf(v.x); v.y = rtf(v.y); v.z = rtf(v.z); v.w = rtf(v.w);
        dst[c] = v;
    }
}

__global__ void dot_scalar_k(const float* __restrict__ a, const float* __restrict__ b,
                             float* __restrict__ out, int K)
{
    __shared__ float sh[128];
    float s = 0.f;
    for (int c = threadIdx.x; c < K; c += 128) s += a[c] * b[c];
    sh[threadIdx.x] = s; __syncthreads();
    for (int o = 64; o > 0; o >>= 1) {
        if (threadIdx.x < o) sh[threadIdx.x] += sh[threadIdx.x + o];
        __syncthreads();
    }
    if (threadIdx.x == 0) *out = sh[0];
}

__global__ void rowdots_k(const float* __restrict__ X, int ldx,
                          const float* __restrict__ v1, const float* __restrict__ v2,
                          const float* __restrict__ cptr, float alpha,
                          float* __restrict__ o1, float* __restrict__ o2, int K)
{
    int row = blockIdx.x;
    const float* x = X + (long)row * ldx;
    float s1 = 0.f, s2 = 0.f;
    for (int c = threadIdx.x; c < K; c += 128) {
        float xv = x[c];
        s1 += xv * v1[c];
        s2 += xv * v2[c];
    }
    __shared__ float r1[128], r2[128];
    r1[threadIdx.x] = s1; r2[threadIdx.x] = s2; __syncthreads();
    for (int o = 64; o > 0; o >>= 1) {
        if (threadIdx.x < o) { r1[threadIdx.x] += r1[threadIdx.x + o]; r2[threadIdx.x] += r2[threadIdx.x + o]; }
        __syncthreads();
    }
    if (threadIdx.x == 0) {
        float t = *cptr + r1[0];
        o1[row] = (t >= 0.f) ? t : alpha * t;
        o2[row] = r2[0];
    }
}

__global__ void rowdot_k(const float* __restrict__ X, const float* __restrict__ v,
                         float* __restrict__ o, int K)
{
    int row = blockIdx.x;
    const float* x = X + (long)row * K;
    float s = 0.f;
    for (int c = threadIdx.x; c < K; c += 128) s += x[c] * v[c];
    __shared__ float sh[128];
    sh[threadIdx.x] = s; __syncthreads();
    for (int o2 = 64; o2 > 0; o2 >>= 1) {
        if (threadIdx.x < o2) sh[threadIdx.x] += sh[threadIdx.x + o2];
        __syncthreads();
    }
    if (threadIdx.x == 0) o[row] = sh[0];
}

// two per-batch maxes in one pass
__global__ void bmax2_k(const float* __restrict__ X, const float* __restrict__ Y,
                        float* __restrict__ ox, float* __restrict__ oy, int len)
{
    __shared__ float shx[256], shy[256];
    int b = blockIdx.x;
    const float* x = X + (long)b * len;
    const float* y = Y + (long)b * len;
    float mx = -3.0e38f, my = -3.0e38f;
    for (int i = threadIdx.x; i < len; i += 256) {
        mx = fmaxf(mx, x[i]);
        my = fmaxf(my, y[i]);
    }
    shx[threadIdx.x] = mx; shy[threadIdx.x] = my; __syncthreads();
    for (int o = 128; o > 0; o >>= 1) {
        if (threadIdx.x < o) {
            shx[threadIdx.x] = fmaxf(shx[threadIdx.x], shx[threadIdx.x + o]);
            shy[threadIdx.x] = fmaxf(shy[threadIdx.x], shy[threadIdx.x + o]);
        }
        __syncthreads();
    }
    if (threadIdx.x == 0) { ox[b] = shx[0]; oy[b] = shy[0]; }
}

__global__ void bmax_k(const float* __restrict__ X, float* __restrict__ out, int len)
{
    __shared__ float sh[256];
    int b = blockIdx.x;
    const float* x = X + (long)b * len;
    float m = -3.0e38f;
    for (int i = threadIdx.x; i < len; i += 256) m = fmaxf(m, x[i]);
    sh[threadIdx.x] = m; __syncthreads();
    for (int o = 128; o > 0; o >>= 1) {
        if (threadIdx.x < o) sh[threadIdx.x] = fmaxf(sh[threadIdx.x], sh[threadIdx.x + o]);
        __syncthreads();
    }
    if (threadIdx.x == 0) out[b] = sh[0];
}

__global__ void build_y_k(const float* __restrict__ X, int ldx,
                          const float* __restrict__ s1, const float* __restrict__ s1max,
                          float* __restrict__ y)
{
    int row = blockIdx.x;
    int b = row >> 10;
    float w = expf(s1[row] - s1max[b]);
    const float* x = X + (long)row * ldx;
    float* yy = y + (long)row * YW;
    for (int c = threadIdx.x; c < YW; c += 128)
        yy[c] = (c < Ff) ? rtf(w * x[c]) : ((c == Ff) ? rtf(w) : 0.f);
}

__global__ void attn_build_k(const float* __restrict__ HT, const float* __restrict__ sn,
                             const float* __restrict__ se, const float* __restrict__ snmax,
                             const float* __restrict__ semax, const float* __restrict__ invZe,
                             float* __restrict__ u2, float* __restrict__ zpart, float alpha)
{
    __shared__ float t[32][33];
    int b  = blockIdx.z;
    int n0 = blockIdx.x * 32, e0 = blockIdx.y * 32;
    int tx = threadIdx.x, ty = threadIdx.y;   // (32,8)

    float sh = snmax[b] + semax[b];
    sh = (sh >= 0.f) ? sh : alpha * sh;

    const float* src = HT + (long)b * Ee * Nn;
    float snv = sn[(long)b * Nn + n0 + tx];
#pragma unroll
    for (int i = 0; i < 32; i += 8) {
        int e = e0 + ty + i;
        float sev = se[(long)b * Ee + e];
        float ht  = src[(long)e * Nn + n0 + tx];
        float v = snv + sev;
        v = (v >= 0.f) ? v : alpha * v;
        t[ty + i][tx] = (ht > 0.f) ? expf(v - sh) : 0.f;
    }
    __syncthreads();

    float iz = invZe[(long)b * Ee + e0 + tx];
    float* dst = u2 + (long)b * Nn * Ee;
#pragma unroll
    for (int i = 0; i < 32; i += 8) {
        int n = n0 + ty + i;
        dst[(long)n * Ee + e0 + tx] = rtf(t[tx][ty + i] * iz);
    }

    if (ty == 0) {
        float s = 0.f;
#pragma unroll
        for (int e = 0; e < 32; ++e) s += t[e][tx];
        zpart[((long)b * Nn + n0 + tx) * 16 + blockIdx.y] = s;
    }
}

__global__ void zsum_k(const float* __restrict__ zpart, float* __restrict__ invZn)
{
    int i = blockIdx.x * 256 + threadIdx.x;
    if (i < ROWS) {
        float s = 0.f;
#pragma unroll
        for (int j = 0; j < 16; ++j) s += zpart[(long)i * 16 + j];
        invZn[i] = (s > 0.f) ? 1.f / s : 0.f;
    }
}

__global__ void concat_k(const float* __restrict__ px4, const float* __restrict__ sem,
                         float* __restrict__ comb)
{
    int row = blockIdx.x;
    float* dst = comb + (long)row * (2 * HH);
    const float* p = px4 + (long)row * 600;
    const float* s = sem + (long)row * HH;
    for (int c = threadIdx.x; c < HH; c += 128) {
        dst[c]      = rtf(p[c]);
        dst[HH + c] = rtf(s[c]);
    }
}

__global__ void final_k(const float* __restrict__ hpre, const float* __restrict__ px4,
                        const float* __restrict__ sem, const float* __restrict__ ln_g,
                        const float* __restrict__ ln_b, const float* __restrict__ A2,
                        const float* __restrict__ b2, float* __restrict__ out)
{
    int row = blockIdx.x;
    int tid = threadIdx.x;
    __shared__ float hs[HH];
    __shared__ float red[128];
    const float* hp = hpre + (long)row * HH;

    float s = 0.f;
    for (int c = tid; c < HH; c += 128) {
        float t = tanhf(hp[c]);
        hs[c] = t;
        s += t;
    }
    red[tid] = s; __syncthreads();
    for (int o = 64; o > 0; o >>= 1) {
        if (tid < o) red[tid] += red[tid + o];
        __syncthreads();
    }
    float mean = red[0] / (float)HH;
    __syncthreads();

    float vs = 0.f;
    for (int c = tid; c < HH; c += 128) { float d = hs[c] - mean; vs += d * d; }
    red[tid] = vs; __syncthreads();
    for (int o = 64; o > 0; o >>= 1) {
        if (tid < o) red[tid] += red[tid + o];
        __syncthreads();
    }
    float rstd = rsqrtf(red[0] / (float)HH + 1e-5f);
    __syncthreads();

    float gdot = 0.f;
    for (int c = tid; c < HH; c += 128) {
        float hn = (hs[c] - mean) * rstd * ln_g[c] + ln_b[c];
        gdot += hn * A2[c];
    }
    red[tid] = gdot; __syncthreads();
    for (int o = 64; o > 0; o >>= 1) {
        if (tid < o) red[tid] += red[tid + o];
        __syncthreads();
    }
    float gate = 1.f / (1.f + expf(-(red[0] + b2[0])));
    __syncthreads();

    const float* p = px4 + (long)row * 600;
    const float* se = sem + (long)row * HH;
    float* o = out + (long)row * HH;
    for (int c = tid; c < HH; c += 128)
        o[c] = gate * se[c] + (1.f - gate) * p[c];
}

// ---------------- launcher ---------------------------------------------------
extern "C" void kernel_launch(void* const* d_in, const int* in_sizes, int n_in,
                              void* d_out, int out_size)
{
    const int*   inp  = (const int*)d_in[0];
    const float* HT   = (const float*)d_in[1];
    const float* emb  = (const float*)d_in[2];
    const float* Wp   = (const float*)d_in[3];
    const float* bp   = (const float*)d_in[4];
    const float* w2_1 = (const float*)d_in[5];
    const float* w3_1 = (const float*)d_in[6];
    const float* wc1  = (const float*)d_in[7];
    const float* a11  = (const float*)d_in[8];
    const float* a21  = (const float*)d_in[9];
    const float* W2t  = (const float*)d_in[10];
    const float* w2_2 = (const float*)d_in[11];
    const float* w3_2 = (const float*)d_in[12];
    const float* wc2  = (const float*)d_in[13];
    const float* a12  = (const float*)d_in[14];
    const float* a22  = (const float*)d_in[15];
    const float* A1   = (const float*)d_in[16];
    const float* b1   = (const float*)d_in[17];
    const float* ln_g = (const float*)d_in[18];
    const float* ln_b = (const float*)d_in[19];
    const float* A2   = (const float*)d_in[20];
    const float* b2   = (const float*)d_in[21];
    float* outp = (float*)d_out;

    static bool attr_done = false;
    if (!attr_done) {
        cudaFuncSetAttribute((const void*)mma_gemm_k<false, 0, false, false>,
                             cudaFuncAttributeMaxDynamicSharedMemorySize, SMEMB);
        cudaFuncSetAttribute((const void*)mma_gemm_k<false, 0, true, true>,
                             cudaFuncAttributeMaxDynamicSharedMemorySize, SMEMB);
        cudaFuncSetAttribute((const void*)mma_gemm_k<false, 1, true, false>,
                             cudaFuncAttributeMaxDynamicSharedMemorySize, SMEMB);
        cudaFuncSetAttribute((const void*)mma_gemm_k<true, 0, false, false>,
                             cudaFuncAttributeMaxDynamicSharedMemorySize, SMEMB);
        attr_done = true;
    }

    float *hidden, *px4, *xx, *s1, *sn, *se, *y, *edge, *e4, *u2, *zpart,
          *invZe, *invZn, *x1, *sem, *comb, *hpre, *gc, *s1max, *snmax, *semax, *wt;
    cudaGetSymbolAddress((void**)&hidden, g_hidden);
    cudaGetSymbolAddress((void**)&px4,    g_px4);
    cudaGetSymbolAddress((void**)&xx,     g_xx);
    cudaGetSymbolAddress((void**)&s1,     g_s1);
    cudaGetSymbolAddress((void**)&sn,     g_sn);
    cudaGetSymbolAddress((void**)&se,     g_se);
    cudaGetSymbolAddress((void**)&y,      g_y);
    cudaGetSymbolAddress((void**)&edge,   g_edge);
    cudaGetSymbolAddress((void**)&e4,     g_e4);
    cudaGetSymbolAddress((void**)&u2,     g_u2);
    cudaGetSymbolAddress((void**)&zpart,  g_zpart);
    cudaGetSymbolAddress((void**)&invZe,  g_invZe);
    cudaGetSymbolAddress((void**)&invZn,  g_invZn);
    cudaGetSymbolAddress((void**)&x1,     g_x1);
    cudaGetSymbolAddress((void**)&sem,    g_sem);
    cudaGetSymbolAddress((void**)&comb,   g_comb);
    cudaGetSymbolAddress((void**)&hpre,   g_hpre);
    cudaGetSymbolAddress((void**)&gc,     g_c);
    cudaGetSymbolAddress((void**)&s1max,  g_s1max);
    cudaGetSymbolAddress((void**)&snmax,  g_snmax);
    cudaGetSymbolAddress((void**)&semax,  g_semax);
    cudaGetSymbolAddress((void**)&wt,     g_wt);

    float* Wcat1 = wt;                 // 180000
    float* Wcat2 = wt + 180000;        // 180000
    float* w31c  = wt + 360000;        // 90000
    float* w32c  = wt + 450000;        // 90000
    float* A1c   = wt + 540000;        // 180000
    float* b600  = wt + 720000;        // 600

    auto grid = [](int M, int N, int Z) {
        return dim3((N + 63) / 64, (M + 127) / 128, Z);
    };

    // ---- prep (idempotent) ----
    prep_cat_k<<<(180000 + 255) / 256, 256>>>(Wp,   w2_1, Wcat1, true);
    prep_cat_k<<<(180000 + 255) / 256, 256>>>(w2_2, W2t,  Wcat2, false);
    prep_bias_k<<<3, 256>>>(bp, b600);
    cvt_k<<<(22500 + 255) / 256, 256>>>(w3_1, w31c, 22500);
    cvt_k<<<(22500 + 255) / 256, 256>>>(w3_2, w32c, 22500);
    cvt_k<<<(45000 + 255) / 256, 256>>>(A1,   A1c,  45000);
    dot_scalar_k<<<1, 128>>>(wc1, a11, gc + 0, Ff);
    dot_scalar_k<<<1, 128>>>(wc2, a12, gc + 1, HH);
    gather_k<<<ROWS, 128>>>(inp, emb, hidden);

    // ---- fused [proj | x4] = hidden @ Wcat1 + b600 ----
    mma_gemm_k<false, 0, false, false><<<grid(ROWS, 600, 1), 128, SMEMB>>>(
        hidden, Wcat1, b600, nullptr, px4, nullptr, ROWS, 600, Ff, Ff, 600, 600, 0, 0, 0, 0);

    // ================= layer 1 (alpha 0.1, ELU) ==============================
    rowdots_k<<<ROWS, 128>>>(px4 + 300, 600, a11 + Ff, a21, gc + 0, 0.1f, s1, sn, Ff);
    bmax2_k<<<Bb, 256>>>(s1, sn, s1max, snmax, Nn);
    build_y_k<<<ROWS, 128>>>(hidden, Ff, s1, s1max, y);
    mma_gemm_k<false, 0, true, true><<<grid(Ee, YW, Bb), 128, SMEMB>>>(
        HT, y, nullptr, nullptr, edge, invZe, Ee, YW, Nn, Nn, YW, YW,
        (long)Ee * Nn, (long)Nn * YW, (long)Ee * YW, 0);
    mma_gemm_k<false, 0, false, false><<<grid(EROWS, Ff, 1), 128, SMEMB>>>(
        edge, w31c, nullptr, invZe, e4, nullptr, EROWS, Ff, Ff, YW, Ff, Ff, 0, 0, 0, 0);
    rowdot_k<<<EROWS, 128>>>(e4, a21 + Ff, se, Ff);
    bmax_k<<<Bb, 256>>>(se, semax, Ee);
    attn_build_k<<<dim3(Nn / 32, Ee / 32, Bb), dim3(32, 8)>>>(
        HT, sn, se, snmax, semax, invZe, u2, zpart, 0.1f);
    zsum_k<<<(ROWS + 255) / 256, 256>>>(zpart, invZn);
    mma_gemm_k<false, 1, true, false><<<grid(Nn, Ff, Bb), 128, SMEMB>>>(
        u2, edge, nullptr, invZn, x1, nullptr, Nn, Ff, Ee, Ee, YW, Ff,
        (long)Nn * Ee, (long)Ee * YW, (long)Nn * Ff, Nn);

    // ================= layer 2 (alpha 0.2, transfer) =========================
    mma_gemm_k<false, 0, false, false><<<grid(ROWS, 600, 1), 128, SMEMB>>>(
        x1, Wcat2, nullptr, nullptr, xx, nullptr, ROWS, 600, Ff, Ff, 600, 600, 0, 0, 0, 0);
    rowdots_k<<<ROWS, 128>>>(xx, 600, a12 + HH, a22, gc + 1, 0.2f, s1, sn, HH);
    bmax2_k<<<Bb, 256>>>(s1, sn, s1max, snmax, Nn);
    build_y_k<<<ROWS, 128>>>(xx + 300, 600, s1, s1max, y);
    mma_gemm_k<false, 0, true, true><<<grid(Ee, YW, Bb), 128, SMEMB>>>(
        HT, y, nullptr, nullptr, edge, invZe, Ee, YW, Nn, Nn, YW, YW,
        (long)Ee * Nn, (long)Nn * YW, (long)Ee * YW, 0);
    mma_gemm_k<false, 0, false, false><<<grid(EROWS, HH, 1), 128, SMEMB>>>(
        edge, w32c, nullptr, invZe, e4, nullptr, EROWS, HH, HH, YW, HH, HH, 0, 0, 0, 0);
    rowdot_k<<<EROWS, 128>>>(e4, a22 + HH, se, HH);
    bmax_k<<<Bb, 256>>>(se, semax, Ee);
    attn_build_k<<<dim3(Nn / 32, Ee / 32, Bb), dim3(32, 8)>>>(
        HT, sn, se, snmax, semax, invZe, u2, zpart, 0.2f);
    zsum_k<<<(ROWS + 255) / 256, 256>>>(zpart, invZn);
    mma_gemm_k<false, 0, false, false><<<grid(Nn, HH, Bb), 128, SMEMB>>>(
        u2, edge, nullptr, invZn, sem, nullptr, Nn, HH, Ee, Ee, YW, HH,
        (long)Nn * Ee, (long)Ee * YW, (long)Nn * HH, Nn);

    // ================= head ==================================================
    concat_k<<<ROWS, 128>>>(px4, sem, comb);
    mma_gemm_k<true, 0, false, false><<<grid(ROWS, HH, 1), 128, SMEMB>>>(
        comb, A1c, b1, nullptr, hpre, nullptr, ROWS, HH, 2 * HH, 2 * HH, 2 * HH, HH, 0, 0, 0, 0);
    final_k<<<ROWS, 128>>>(hpre, px4, sem, ln_g, ln_b, A2, b2, outp);
}

// round 10
// speedup vs baseline: 1.6227x; 1.3441x over previous
#include <cuda_runtime.h>
#include <cuda_fp16.h>
#include <math.h>

#define Bb 32
#define Nn 1024
#define Ee 512
#define Ff 300
#define HH 300
#define Vv 50001

constexpr int ROWS  = Bb * Nn;   // 32768
constexpr int EROWS = Bb * Ee;   // 16384
constexpr int YW    = 304;       // padded row width (300 data + w/Z + pad)
constexpr int FfP   = 304;       // padded K for 300-dims
constexpr int SSTGH = 128 * 40 + 64 * 40;      // halves per stage (A + B)
constexpr int SMEMB = SSTGH * 3 * 2;           // 46080 B, 3 stages

// ---------------- scratch ----------------------------------------------------
__device__ __align__(16) __half g_hidden_h[ROWS * FfP];
__device__ __align__(16) __half g_HT_h   [Bb * Ee * Nn];
__device__ float g_px4   [ROWS * 600];   // [proj | x4] layer1 (fp32: feeds final/rowdots)
__device__ __align__(16) __half g_xx_h  [ROWS * 600];   // [x4 | xW] layer2
__device__ float g_s1    [ROWS];
__device__ float g_sn    [ROWS];
__device__ float g_se    [EROWS];
__device__ __align__(16) __half g_y_h   [ROWS * YW];
__device__ __align__(16) __half g_edge_h[EROWS * YW];
__device__ float g_e4    [EROWS * Ff];
__device__ __align__(16) __half g_u2_h  [Bb * Nn * Ee];
__device__ float g_zpart [ROWS * 16];
__device__ float g_invZe [EROWS];
__device__ float g_invZn [ROWS];
__device__ __align__(16) __half g_x1_h  [ROWS * FfP];
__device__ float g_sem   [ROWS * HH];
__device__ __align__(16) __half g_comb_h[ROWS * 600];
__device__ float g_hpre  [ROWS * HH];
__device__ float g_c     [2];
__device__ float g_s1max [Bb];
__device__ float g_snmax [Bb];
__device__ float g_semax [Bb];
__device__ __align__(16) __half g_wt_h  [730000];   // prepped fp16 weights
__device__ float g_b600  [600];

// ---------------- helpers ----------------------------------------------------
__device__ __forceinline__ void mma_f16(float* d, const unsigned* a, const unsigned* b) {
    asm volatile(
        "mma.sync.aligned.m16n8k16.row.col.f32.f16.f16.f32 "
        "{%0,%1,%2,%3}, {%4,%5,%6,%7}, {%8,%9}, {%0,%1,%2,%3};"
        : "+f"(d[0]), "+f"(d[1]), "+f"(d[2]), "+f"(d[3])
        : "r"(a[0]), "r"(a[1]), "r"(a[2]), "r"(a[3]), "r"(b[0]), "r"(b[1]));
}

__device__ __forceinline__ void cp16(void* smem_dst, const void* gsrc, bool pred) {
    unsigned d = (unsigned)__cvta_generic_to_shared(smem_dst);
    int sz = pred ? 16 : 0;
    asm volatile("cp.async.ca.shared.global [%0], [%1], 16, %2;" :: "r"(d), "l"(gsrc), "r"(sz));
}

// ---------------- fp16 tensor-core GEMM, cp.async 3-stage --------------------
// C = rowscale(A@B) (+bias) (ELU). A:[M,K] fp16 lda. B: [K,N] (or [N,K] if TRANSB) fp16.
// Block 128x64, 128 thr, warp grid 2x2, warp tile 64x32. K%8==0 required (padded).
template <bool TRANSB, int ACT, bool OUTH, bool WRZ>
__global__ void __launch_bounds__(128)
hgemm_k(const __half* __restrict__ A, const __half* __restrict__ B,
        const float* __restrict__ bias, const float* __restrict__ rowscale,
        void* __restrict__ Cv, float* __restrict__ zout,
        int M, int N, int K, int lda, int ldb, int ldc,
        long sA, long sB, long sC, long sScale)
{
    extern __shared__ __half smh[];
    constexpr int BOFF = 128 * 40;

    A += (long)blockIdx.z * sA;
    B += (long)blockIdx.z * sB;
    const float* rs = rowscale ? rowscale + (long)blockIdx.z * sScale : nullptr;

    const int tid  = threadIdx.x;
    const int warp = tid >> 5, lane = tid & 31;
    const int g    = lane >> 2, tig = lane & 3;
    const int wm   = warp >> 1, wn = warp & 1;
    const int m0   = blockIdx.y * 128, n0 = blockIdx.x * 64;

    float acc[4][4][4];
#pragma unroll
    for (int i = 0; i < 4; ++i)
#pragma unroll
        for (int j = 0; j < 4; ++j)
#pragma unroll
            for (int l = 0; l < 4; ++l) acc[i][j][l] = 0.f;

    const int kt = (K + 31) / 32;

    auto issue = [&](int t, int st) {
        int k0 = t * 32;
        __half* As = smh + st * SSTGH;
        __half* Bs = As + BOFF;
#pragma unroll
        for (int i = 0; i < 4; ++i) {          // A: 128 rows x 4 chunks(8h)
            int f = tid + i * 128;
            int row = f >> 2, ck = (f & 3) * 8;
            int gm = m0 + row, gk = k0 + ck;
            bool p = (gm < M) && (gk < K);
            cp16(&As[row * 40 + ck], p ? (A + (long)gm * lda + gk) : A, p);
        }
#pragma unroll
        for (int i = 0; i < 2; ++i) {
            int f = tid + i * 128;
            if (TRANSB) {                       // [n=64][k: 4 chunks]
                int nr = f >> 2, ck = (f & 3) * 8;
                int gn = n0 + nr, gk = k0 + ck;
                bool p = (gn < N) && (gk < K);
                cp16(&Bs[nr * 40 + ck], p ? (B + (long)gn * ldb + gk) : B, p);
            } else {                            // [k=32][n: 8 chunks]
                int row = f >> 3, cn = (f & 7) * 8;
                int gk = k0 + row, gn = n0 + cn;
                bool p = (gk < K) && (gn < N);
                cp16(&Bs[row * 72 + cn], p ? (B + (long)gk * ldb + gn) : B, p);
            }
        }
        asm volatile("cp.async.commit_group;");
    };

    issue(0, 0);
    if (kt > 1) issue(1, 1);

    for (int t = 0; t < kt; ++t) {
        asm volatile("cp.async.wait_group 1;");
        __syncthreads();
        if (t + 2 < kt) issue(t + 2, (t + 2) % 3);

        const __half* As = smh + (t % 3) * SSTGH;
        const __half* Bs = As + BOFF;
#pragma unroll
        for (int ks = 0; ks < 2; ++ks) {
            const int kb = ks * 16;
            unsigned af[4][4], bf[4][2];
#pragma unroll
            for (int mi = 0; mi < 4; ++mi) {
                int r = wm * 64 + mi * 16 + g;
                af[mi][0] = *(const unsigned*)&As[(r    ) * 40 + kb + 2 * tig];
                af[mi][1] = *(const unsigned*)&As[(r + 8) * 40 + kb + 2 * tig];
                af[mi][2] = *(const unsigned*)&As[(r    ) * 40 + kb + 2 * tig + 8];
                af[mi][3] = *(const unsigned*)&As[(r + 8) * 40 + kb + 2 * tig + 8];
            }
#pragma unroll
            for (int ni = 0; ni < 4; ++ni) {
                int c = wn * 32 + ni * 8 + g;
                if (TRANSB) {
                    bf[ni][0] = *(const unsigned*)&Bs[c * 40 + kb + 2 * tig];
                    bf[ni][1] = *(const unsigned*)&Bs[c * 40 + kb + 2 * tig + 8];
                } else {
                    unsigned lo0 = *(const unsigned short*)&Bs[(kb + 2 * tig    ) * 72 + c];
                    unsigned hi0 = *(const unsigned short*)&Bs[(kb + 2 * tig + 1) * 72 + c];
                    bf[ni][0] = lo0 | (hi0 << 16);
                    unsigned lo1 = *(const unsigned short*)&Bs[(kb + 2 * tig + 8) * 72 + c];
                    unsigned hi1 = *(const unsigned short*)&Bs[(kb + 2 * tig + 9) * 72 + c];
                    bf[ni][1] = lo1 | (hi1 << 16);
                }
            }
#pragma unroll
            for (int mi = 0; mi < 4; ++mi)
#pragma unroll
                for (int ni = 0; ni < 4; ++ni)
                    mma_f16(acc[mi][ni], af[mi], bf[ni]);
        }
        __syncthreads();
    }

#pragma unroll
    for (int mi = 0; mi < 4; ++mi) {
#pragma unroll
        for (int ni = 0; ni < 4; ++ni) {
            int r = m0 + wm * 64 + mi * 16 + g;
            int c = n0 + wn * 32 + ni * 8 + tig * 2;
            if (c >= N) continue;
            float bx = bias ? bias[c] : 0.f;
            float by = bias ? bias[c + 1] : 0.f;
#pragma unroll
            for (int h = 0; h < 2; ++h) {
                int rr = r + h * 8;
                if (rr >= M) continue;
                float sc = rs ? rs[rr] : 1.f;
                float vx = acc[mi][ni][h * 2 + 0] * sc + bx;
                float vy = acc[mi][ni][h * 2 + 1] * sc + by;
                if (ACT == 1) {
                    vx = (vx > 0.f) ? vx : expm1f(vx);
                    vy = (vy > 0.f) ? vy : expm1f(vy);
                }
                if (WRZ && c == Ff)
                    zout[(long)blockIdx.z * Ee + rr] = (vx > 0.f) ? 1.f / vx : 0.f;
                if (OUTH) {
                    __half* C = (__half*)Cv + (long)blockIdx.z * sC;
                    *(__half2*)(C + (long)rr * ldc + c) = __floats2half2_rn(vx, vy);
                } else {
                    float* C = (float*)Cv + (long)blockIdx.z * sC;
                    *(float2*)(C + (long)rr * ldc + c) = make_float2(vx, vy);
                }
            }
        }
    }
}

// ---------------- prep kernels -----------------------------------------------
__global__ void cvt_h4_k(const float* __restrict__ src, __half* __restrict__ dst, int n4)
{
    int i = blockIdx.x * 256 + threadIdx.x;
    if (i < n4) {
        float4 v = ((const float4*)src)[i];
        __half2* d = (__half2*)(dst + (long)i * 4);
        d[0] = __floats2half2_rn(v.x, v.y);
        d[1] = __floats2half2_rn(v.z, v.w);
    }
}

__global__ void cvt_half_k(const float* __restrict__ src, __half* __restrict__ dst, int n)
{
    int i = blockIdx.x * 256 + threadIdx.x;
    if (i < n) dst[i] = __float2half(src[i]);
}

// Wcat [600][304]: k<300 ? (j<300 ? (transL? L[j][k] : L[k][j]) : R[k][j-300]) : 0
__global__ void prep_cat_h(const float* __restrict__ L, const float* __restrict__ R,
                           __half* __restrict__ W, bool transL)
{
    int i = blockIdx.x * 256 + threadIdx.x;
    if (i >= 600 * FfP) return;
    int j = i / FfP, k = i % FfP;
    float v = 0.f;
    if (k < 300)
        v = (j < 300) ? (transL ? L[j * 300 + k] : L[k * 300 + j])
                      : R[k * 300 + (j - 300)];
    W[i] = __float2half(v);
}

// Wt [300][304] = S^T padded
__global__ void prep_t_h(const float* __restrict__ S, __half* __restrict__ W)
{
    int i = blockIdx.x * 256 + threadIdx.x;
    if (i >= 300 * FfP) return;
    int n = i / FfP, k = i % FfP;
    W[i] = __float2half((k < 300) ? S[k * 300 + n] : 0.f);
}

__global__ void prep_bias_k(const float* __restrict__ bp, float* __restrict__ b600)
{
    int i = blockIdx.x * 256 + threadIdx.x;
    if (i < 600) b600[i] = (i < 300) ? bp[i] : 0.f;
}

__global__ void gather_k(const int* __restrict__ idx,
                         const float* __restrict__ emb, __half* __restrict__ out)
{
    int row = blockIdx.x;
    int id = idx[row];
    id = max(0, min(id, Vv - 1));
    const float* src = emb + (long)id * Ff;
    __half2* dst = (__half2*)(out + (long)row * FfP);
    for (int c = threadIdx.x; c < FfP / 2; c += 128) {
        float x0 = (2 * c     < Ff) ? src[2 * c]     : 0.f;
        float x1 = (2 * c + 1 < Ff) ? src[2 * c + 1] : 0.f;
        dst[c] = __floats2half2_rn(x0, x1);
    }
}

__global__ void dot_scalar_k(const float* __restrict__ a, const float* __restrict__ b,
                             float* __restrict__ out, int K)
{
    __shared__ float sh[128];
    float s = 0.f;
    for (int c = threadIdx.x; c < K; c += 128) s += a[c] * b[c];
    sh[threadIdx.x] = s; __syncthreads();
    for (int o = 64; o > 0; o >>= 1) {
        if (threadIdx.x < o) sh[threadIdx.x] += sh[threadIdx.x + o];
        __syncthreads();
    }
    if (threadIdx.x == 0) *out = sh[0];
}

__device__ __forceinline__ float ldf(const float* p) { return *p; }
__device__ __forceinline__ float ldf(const __half* p) { return __half2float(*p); }

template <typename T>
__global__ void rowdots_k(const T* __restrict__ X, int ldx,
                          const float* __restrict__ v1, const float* __restrict__ v2,
                          const float* __restrict__ cptr, float alpha,
                          float* __restrict__ o1, float* __restrict__ o2, int K)
{
    int row = blockIdx.x;
    const T* x = X + (long)row * ldx;
    float s1 = 0.f, s2 = 0.f;
    for (int c = threadIdx.x; c < K; c += 128) {
        float xv = ldf(x + c);
        s1 += xv * v1[c];
        s2 += xv * v2[c];
    }
    __shared__ float r1[128], r2[128];
    r1[threadIdx.x] = s1; r2[threadIdx.x] = s2; __syncthreads();
    for (int o = 64; o > 0; o >>= 1) {
        if (threadIdx.x < o) { r1[threadIdx.x] += r1[threadIdx.x + o]; r2[threadIdx.x] += r2[threadIdx.x + o]; }
        __syncthreads();
    }
    if (threadIdx.x == 0) {
        float t = *cptr + r1[0];
        o1[row] = (t >= 0.f) ? t : alpha * t;
        o2[row] = r2[0];
    }
}

__global__ void rowdot_k(const float* __restrict__ X, const float* __restrict__ v,
                         float* __restrict__ o, int K)
{
    int row = blockIdx.x;
    const float* x = X + (long)row * K;
    float s = 0.f;
    for (int c = threadIdx.x; c < K; c += 128) s += x[c] * v[c];
    __shared__ float sh[128];
    sh[threadIdx.x] = s; __syncthreads();
    for (int o2 = 64; o2 > 0; o2 >>= 1) {
        if (threadIdx.x < o2) sh[threadIdx.x] += sh[threadIdx.x + o2];
        __syncthreads();
    }
    if (threadIdx.x == 0) o[row] = sh[0];
}

__global__ void bmax2_k(const float* __restrict__ X, const float* __restrict__ Y,
                        float* __restrict__ ox, float* __restrict__ oy, int len)
{
    __shared__ float shx[256], shy[256];
    int b = blockIdx.x;
    const float* x = X + (long)b * len;
    const float* y = Y + (long)b * len;
    float mx = -3.0e38f, my = -3.0e38f;
    for (int i = threadIdx.x; i < len; i += 256) {
        mx = fmaxf(mx, x[i]);
        my = fmaxf(my, y[i]);
    }
    shx[threadIdx.x] = mx; shy[threadIdx.x] = my; __syncthreads();
    for (int o = 128; o > 0; o >>= 1) {
        if (threadIdx.x < o) {
            shx[threadIdx.x] = fmaxf(shx[threadIdx.x], shx[threadIdx.x + o]);
            shy[threadIdx.x] = fmaxf(shy[threadIdx.x], shy[threadIdx.x + o]);
        }
        __syncthreads();
    }
    if (threadIdx.x == 0) { ox[b] = shx[0]; oy[b] = shy[0]; }
}

__global__ void bmax_k(const float* __restrict__ X, float* __restrict__ out, int len)
{
    __shared__ float sh[256];
    int b = blockIdx.x;
    const float* x = X + (long)b * len;
    float m = -3.0e38f;
    for (int i = threadIdx.x; i < len; i += 256) m = fmaxf(m, x[i]);
    sh[threadIdx.x] = m; __syncthreads();
    for (int o = 128; o > 0; o >>= 1) {
        if (threadIdx.x < o) sh[threadIdx.x] = fmaxf(sh[threadIdx.x], sh[threadIdx.x + o]);
        __syncthreads();
    }
    if (threadIdx.x == 0) out[b] = sh[0];
}

__global__ void build_y_k(const __half* __restrict__ X, int ldx,
                          const float* __restrict__ s1, const float* __restrict__ s1max,
                          __half* __restrict__ y)
{
    int row = blockIdx.x;
    int b = row >> 10;
    float w = expf(s1[row] - s1max[b]);
    const __half* x = X + (long)row * ldx;
    __half* yy = y + (long)row * YW;
    for (int c = threadIdx.x; c < YW; c += 128) {
        float v = (c < Ff) ? w * __half2float(x[c]) : ((c == Ff) ? w : 0.f);
        yy[c] = __float2half(v);
    }
}

__global__ void attn_build_k(const float* __restrict__ HT, const float* __restrict__ sn,
                             const float* __restrict__ se, const float* __restrict__ snmax,
                             const float* __restrict__ semax, const float* __restrict__ invZe,
                             __half* __restrict__ u2, float* __restrict__ zpart, float alpha)
{
    __shared__ float t[32][33];
    int b  = blockIdx.z;
    int n0 = blockIdx.x * 32, e0 = blockIdx.y * 32;
    int tx = threadIdx.x, ty = threadIdx.y;   // (32,8)

    float sh = snmax[b] + semax[b];
    sh = (sh >= 0.f) ? sh : alpha * sh;

    const float* src = HT + (long)b * Ee * Nn;
    float snv = sn[(long)b * Nn + n0 + tx];
#pragma unroll
    for (int i = 0; i < 32; i += 8) {
        int e = e0 + ty + i;
        float sev = se[(long)b * Ee + e];
        float ht  = src[(long)e * Nn + n0 + tx];
        float v = snv + sev;
        v = (v >= 0.f) ? v : alpha * v;
        t[ty + i][tx] = (ht > 0.f) ? expf(v - sh) : 0.f;
    }
    __syncthreads();

    float iz = invZe[(long)b * Ee + e0 + tx];
    __half* dst = u2 + (long)b * Nn * Ee;
#pragma unroll
    for (int i = 0; i < 32; i += 8) {
        int n = n0 + ty + i;
        dst[(long)n * Ee + e0 + tx] = __float2half(t[tx][ty + i] * iz);
    }

    if (ty == 0) {
        float s = 0.f;
#pragma unroll
        for (int e = 0; e < 32; ++e) s += t[e][tx];
        zpart[((long)b * Nn + n0 + tx) * 16 + blockIdx.y] = s;
    }
}

__global__ void zsum_k(const float* __restrict__ zpart, float* __restrict__ invZn)
{
    int i = blockIdx.x * 256 + threadIdx.x;
    if (i < ROWS) {
        float s = 0.f;
#pragma unroll
        for (int j = 0; j < 16; ++j) s += zpart[(long)i * 16 + j];
        invZn[i] = (s > 0.f) ? 1.f / s : 0.f;
    }
}

__global__ void concat_k(const float* __restrict__ px4, const float* __restrict__ sem,
                         __half* __restrict__ comb)
{
    int row = blockIdx.x;
    __half* dst = comb + (long)row * 600;
    const float* p = px4 + (long)row * 600;
    const float* s = sem + (long)row * HH;
    for (int c = threadIdx.x; c < HH; c += 128) {
        dst[c]      = __float2half(p[c]);
        dst[HH + c] = __float2half(s[c]);
    }
}

__global__ void final_k(const float* __restrict__ hpre, const float* __restrict__ px4,
                        const float* __restrict__ sem, const float* __restrict__ ln_g,
                        const float* __restrict__ ln_b, const float* __restrict__ A2,
                        const float* __restrict__ b2, float* __restrict__ out)
{
    int row = blockIdx.x;
    int tid = threadIdx.x;
    __shared__ float hs[HH];
    __shared__ float red[128];
    const float* hp = hpre + (long)row * HH;

    float s = 0.f;
    for (int c = tid; c < HH; c += 128) {
        float t = tanhf(hp[c]);
        hs[c] = t;
        s += t;
    }
    red[tid] = s; __syncthreads();
    for (int o = 64; o > 0; o >>= 1) {
        if (tid < o) red[tid] += red[tid + o];
        __syncthreads();
    }
    float mean = red[0] / (float)HH;
    __syncthreads();

    float vs = 0.f;
    for (int c = tid; c < HH; c += 128) { float d = hs[c] - mean; vs += d * d; }
    red[tid] = vs; __syncthreads();
    for (int o = 64; o > 0; o >>= 1) {
        if (tid < o) red[tid] += red[tid + o];
        __syncthreads();
    }
    float rstd = rsqrtf(red[0] / (float)HH + 1e-5f);
    __syncthreads();

    float gdot = 0.f;
    for (int c = tid; c < HH; c += 128) {
        float hn = (hs[c] - mean) * rstd * ln_g[c] + ln_b[c];
        gdot += hn * A2[c];
    }
    red[tid] = gdot; __syncthreads();
    for (int o = 64; o > 0; o >>= 1) {
        if (tid < o) red[tid] += red[tid + o];
        __syncthreads();
    }
    float gate = 1.f / (1.f + expf(-(red[0] + b2[0])));
    __syncthreads();

    const float* p = px4 + (long)row * 600;
    const float* se = sem + (long)row * HH;
    float* o = out + (long)row * HH;
    for (int c = tid; c < HH; c += 128)
        o[c] = gate * se[c] + (1.f - gate) * p[c];
}

// ---------------- launcher ---------------------------------------------------
extern "C" void kernel_launch(void* const* d_in, const int* in_sizes, int n_in,
                              void* d_out, int out_size)
{
    const int*   inp  = (const int*)d_in[0];
    const float* HT   = (const float*)d_in[1];
    const float* emb  = (const float*)d_in[2];
    const float* Wp   = (const float*)d_in[3];
    const float* bp   = (const float*)d_in[4];
    const float* w2_1 = (const float*)d_in[5];
    const float* w3_1 = (const float*)d_in[6];
    const float* wc1  = (const float*)d_in[7];
    const float* a11  = (const float*)d_in[8];
    const float* a21  = (const float*)d_in[9];
    const float* W2t  = (const float*)d_in[10];
    const float* w2_2 = (const float*)d_in[11];
    const float* w3_2 = (const float*)d_in[12];
    const float* wc2  = (const float*)d_in[13];
    const float* a12  = (const float*)d_in[14];
    const float* a22  = (const float*)d_in[15];
    const float* A1   = (const float*)d_in[16];
    const float* b1   = (const float*)d_in[17];
    const float* ln_g = (const float*)d_in[18];
    const float* ln_b = (const float*)d_in[19];
    const float* A2   = (const float*)d_in[20];
    const float* b2   = (const float*)d_in[21];
    float* outp = (float*)d_out;

    static bool attr_done = false;
    if (!attr_done) {
        cudaFuncSetAttribute((const void*)hgemm_k<true, 0, false, false>,
                             cudaFuncAttributeMaxDynamicSharedMemorySize, SMEMB);
        cudaFuncSetAttribute((const void*)hgemm_k<false, 0, true, true>,
                             cudaFuncAttributeMaxDynamicSharedMemorySize, SMEMB);
        cudaFuncSetAttribute((const void*)hgemm_k<false, 1, true, false>,
                             cudaFuncAttributeMaxDynamicSharedMemorySize, SMEMB);
        cudaFuncSetAttribute((const void*)hgemm_k<true, 0, true, false>,
                             cudaFuncAttributeMaxDynamicSharedMemorySize, SMEMB);
        cudaFuncSetAttribute((const void*)hgemm_k<false, 0, false, false>,
                             cudaFuncAttributeMaxDynamicSharedMemorySize, SMEMB);
        attr_done = true;
    }

    __half *hidden_h, *HT_h, *xx_h, *y_h, *edge_h, *u2_h, *x1_h, *comb_h, *wt_h;
    float *px4, *s1, *sn, *se, *e4, *zpart, *invZe, *invZn, *sem, *hpre, *gc,
          *s1max, *snmax, *semax, *b600;
    cudaGetSymbolAddress((void**)&hidden_h, g_hidden_h);
    cudaGetSymbolAddress((void**)&HT_h,   g_HT_h);
    cudaGetSymbolAddress((void**)&px4,    g_px4);
    cudaGetSymbolAddress((void**)&xx_h,   g_xx_h);
    cudaGetSymbolAddress((void**)&s1,     g_s1);
    cudaGetSymbolAddress((void**)&sn,     g_sn);
    cudaGetSymbolAddress((void**)&se,     g_se);
    cudaGetSymbolAddress((void**)&y_h,    g_y_h);
    cudaGetSymbolAddress((void**)&edge_h, g_edge_h);
    cudaGetSymbolAddress((void**)&e4,     g_e4);
    cudaGetSymbolAddress((void**)&u2_h,   g_u2_h);
    cudaGetSymbolAddress((void**)&zpart,  g_zpart);
    cudaGetSymbolAddress((void**)&invZe,  g_invZe);
    cudaGetSymbolAddress((void**)&invZn,  g_invZn);
    cudaGetSymbolAddress((void**)&x1_h,   g_x1_h);
    cudaGetSymbolAddress((void**)&sem,    g_sem);
    cudaGetSymbolAddress((void**)&comb_h, g_comb_h);
    cudaGetSymbolAddress((void**)&hpre,   g_hpre);
    cudaGetSymbolAddress((void**)&gc,     g_c);
    cudaGetSymbolAddress((void**)&s1max,  g_s1max);
    cudaGetSymbolAddress((void**)&snmax,  g_snmax);
    cudaGetSymbolAddress((void**)&semax,  g_semax);
    cudaGetSymbolAddress((void**)&wt_h,   g_wt_h);
    cudaGetSymbolAddress((void**)&b600,   g_b600);

    __half* Wcat1h = wt_h;                     // 600*304 = 182400
    __half* Wcat2h = wt_h + 182400;            // 182400
    __half* w31h   = wt_h + 364800;            // 300*304 = 91200
    __half* w32h   = wt_h + 456000;            // 91200
    __half* A1h    = wt_h + 547200;            // 300*600 = 180000

    auto grid = [](int M, int N, int Z) {
        return dim3((N + 63) / 64, (M + 127) / 128, Z);
    };

    // ---- prep (idempotent) ----
    prep_cat_h<<<(600 * FfP + 255) / 256, 256>>>(Wp,   w2_1, Wcat1h, true);
    prep_cat_h<<<(600 * FfP + 255) / 256, 256>>>(w2_2, W2t,  Wcat2h, false);
    prep_t_h<<<(300 * FfP + 255) / 256, 256>>>(w3_1, w31h);
    prep_t_h<<<(300 * FfP + 255) / 256, 256>>>(w3_2, w32h);
    cvt_half_k<<<(180000 + 255) / 256, 256>>>(A1, A1h, 180000);
    prep_bias_k<<<3, 256>>>(bp, b600);
    cvt_h4_k<<<(Bb * Ee * Nn / 4 + 255) / 256, 256>>>(HT, HT_h, Bb * Ee * Nn / 4);
    dot_scalar_k<<<1, 128>>>(wc1, a11, gc + 0, Ff);
    dot_scalar_k<<<1, 128>>>(wc2, a12, gc + 1, HH);
    gather_k<<<ROWS, 128>>>(inp, emb, hidden_h);

    // ---- fused [proj | x4] = hidden @ Wcat1^T + b600 (fp32 out) ----
    hgemm_k<true, 0, false, false><<<grid(ROWS, 600, 1), 128, SMEMB>>>(
        hidden_h, Wcat1h, b600, nullptr, px4, nullptr,
        ROWS, 600, FfP, FfP, FfP, 600, 0, 0, 0, 0);

    // ================= layer 1 (alpha 0.1, ELU) ==============================
    rowdots_k<float><<<ROWS, 128>>>(px4 + 300, 600, a11 + Ff, a21, gc + 0, 0.1f, s1, sn, Ff);
    bmax2_k<<<Bb, 256>>>(s1, sn, s1max, snmax, Nn);
    build_y_k<<<ROWS, 128>>>(hidden_h, FfP, s1, s1max, y_h);
    hgemm_k<false, 0, true, true><<<grid(Ee, YW, Bb), 128, SMEMB>>>(
        HT_h, y_h, nullptr, nullptr, edge_h, invZe,
        Ee, YW, Nn, Nn, YW, YW, (long)Ee * Nn, (long)Nn * YW, (long)Ee * YW, 0);
    hgemm_k<true, 0, false, false><<<grid(EROWS, 300, 1), 128, SMEMB>>>(
        edge_h, w31h, nullptr, invZe, e4, nullptr,
        EROWS, 300, FfP, YW, FfP, 300, 0, 0, 0, 0);
    rowdot_k<<<EROWS, 128>>>(e4, a21 + Ff, se, Ff);
    bmax_k<<<Bb, 256>>>(se, semax, Ee);
    attn_build_k<<<dim3(Nn / 32, Ee / 32, Bb), dim3(32, 8)>>>(
        HT, sn, se, snmax, semax, invZe, u2_h, zpart, 0.1f);
    zsum_k<<<(ROWS + 255) / 256, 256>>>(zpart, invZn);
    hgemm_k<false, 1, true, false><<<grid(Nn, FfP, Bb), 128, SMEMB>>>(
        u2_h, edge_h, nullptr, invZn, x1_h, nullptr,
        Nn, FfP, Ee, Ee, YW, FfP, (long)Nn * Ee, (long)Ee * YW, (long)Nn * FfP, Nn);

    // ================= layer 2 (alpha 0.2, transfer) =========================
    hgemm_k<true, 0, true, false><<<grid(ROWS, 600, 1), 128, SMEMB>>>(
        x1_h, Wcat2h, nullptr, nullptr, xx_h, nullptr,
        ROWS, 600, FfP, FfP, FfP, 600, 0, 0, 0, 0);
    rowdots_k<__half><<<ROWS, 128>>>(xx_h, 600, a12 + HH, a22, gc + 1, 0.2f, s1, sn, HH);
    bmax2_k<<<Bb, 256>>>(s1, sn, s1max, snmax, Nn);
    build_y_k<<<ROWS, 128>>>(xx_h + 300, 600, s1, s1max, y_h);
    hgemm_k<false, 0, true, true><<<grid(Ee, YW, Bb), 128, SMEMB>>>(
        HT_h, y_h, nullptr, nullptr, edge_h, invZe,
        Ee, YW, Nn, Nn, YW, YW, (long)Ee * Nn, (long)Nn * YW, (long)Ee * YW, 0);
    hgemm_k<true, 0, false, false><<<grid(EROWS, 300, 1), 128, SMEMB>>>(
        edge_h, w32h, nullptr, invZe, e4, nullptr,
        EROWS, 300, FfP, YW, FfP, 300, 0, 0, 0, 0);
    rowdot_k<<<EROWS, 128>>>(e4, a22 + HH, se, HH);
    bmax_k<<<Bb, 256>>>(se, semax, Ee);
    attn_build_k<<<dim3(Nn / 32, Ee / 32, Bb), dim3(32, 8)>>>(
        HT, sn, se, snmax, semax, invZe, u2_h, zpart, 0.2f);
    zsum_k<<<(ROWS + 255) / 256, 256>>>(zpart, invZn);
    hgemm_k<false, 0, false, false><<<grid(Nn, 300, Bb), 128, SMEMB>>>(
        u2_h, edge_h, nullptr, invZn, sem, nullptr,
        Nn, 300, Ee, Ee, YW, 300, (long)Nn * Ee, (long)Ee * YW, (long)Nn * 300, Nn);

    // ================= head ==================================================
    concat_k<<<ROWS, 128>>>(px4, sem, comb_h);
    hgemm_k<true, 0, false, false><<<grid(ROWS, 300, 1), 128, SMEMB>>>(
        comb_h, A1h, b1, nullptr, hpre, nullptr,
        ROWS, 300, 600, 600, 600, 300, 0, 0, 0, 0);
    final_k<<<ROWS, 128>>>(hpre, px4, sem, ln_g, ln_b, A2, b2, outp);
}

// round 11
// speedup vs baseline: 1.6875x; 1.0399x over previous
#include <cuda_runtime.h>
#include <cuda_fp16.h>
#include <math.h>

#define Bb 32
#define Nn 1024
#define Ee 512
#define Ff 300
#define HH 300
#define Vv 50001

constexpr int ROWS  = Bb * Nn;   // 32768
constexpr int EROWS = Bb * Ee;   // 16384
constexpr int YW    = 304;       // padded row width (300 data + w/Z + pad)
constexpr int FfP   = 304;       // padded K for 300-dims
constexpr int SSTGH = 128 * 40 + 64 * 40;      // halves per stage (A + B)
constexpr int SMEMB = SSTGH * 3 * 2;           // 46080 B, 3 stages

// ---------------- scratch ----------------------------------------------------
__device__ __align__(16) __half g_hidden_h[ROWS * FfP];
__device__ __align__(16) __half g_HT_h   [Bb * Ee * Nn];
__device__ float g_px4   [ROWS * 600];
__device__ __align__(16) __half g_xx_h  [ROWS * 600];
__device__ float g_s1    [ROWS];
__device__ float g_sn    [ROWS];
__device__ float g_se    [EROWS];
__device__ __align__(16) __half g_y_h   [ROWS * YW];
__device__ __align__(16) __half g_edge_h[EROWS * YW];
__device__ float g_e4    [EROWS * Ff];
__device__ __align__(16) __half g_u2_h  [Bb * Nn * Ee];
__device__ float g_zpart [ROWS * 16];
__device__ float g_invZe [EROWS];
__device__ float g_invZn [ROWS];
__device__ __align__(16) __half g_x1_h  [ROWS * FfP];
__device__ float g_sem   [ROWS * HH];
__device__ __align__(16) __half g_comb_h[ROWS * 600];
__device__ float g_hpre  [ROWS * HH];
__device__ float g_c     [2];
__device__ float g_s1max [Bb];
__device__ float g_snmax [Bb];
__device__ float g_semax [Bb];
__device__ __align__(16) __half g_wt_h  [730000];
__device__ float g_b600  [600];

// ---------------- helpers ----------------------------------------------------
__device__ __forceinline__ void mma_f16(float* d, const unsigned* a, const unsigned* b) {
    asm volatile(
        "mma.sync.aligned.m16n8k16.row.col.f32.f16.f16.f32 "
        "{%0,%1,%2,%3}, {%4,%5,%6,%7}, {%8,%9}, {%0,%1,%2,%3};"
        : "+f"(d[0]), "+f"(d[1]), "+f"(d[2]), "+f"(d[3])
        : "r"(a[0]), "r"(a[1]), "r"(a[2]), "r"(a[3]), "r"(b[0]), "r"(b[1]));
}

__device__ __forceinline__ void ldmx4(unsigned* r, unsigned addr) {
    asm volatile("ldmatrix.sync.aligned.m8n8.x4.shared.b16 {%0,%1,%2,%3}, [%4];"
                 : "=r"(r[0]), "=r"(r[1]), "=r"(r[2]), "=r"(r[3]) : "r"(addr));
}
__device__ __forceinline__ void ldmx2(unsigned* r, unsigned addr) {
    asm volatile("ldmatrix.sync.aligned.m8n8.x2.shared.b16 {%0,%1}, [%2];"
                 : "=r"(r[0]), "=r"(r[1]) : "r"(addr));
}
__device__ __forceinline__ void ldmx2t(unsigned* r, unsigned addr) {
    asm volatile("ldmatrix.sync.aligned.m8n8.x2.trans.shared.b16 {%0,%1}, [%2];"
                 : "=r"(r[0]), "=r"(r[1]) : "r"(addr));
}

__device__ __forceinline__ void cp16(void* smem_dst, const void* gsrc, bool pred) {
    unsigned d = (unsigned)__cvta_generic_to_shared(smem_dst);
    int sz = pred ? 16 : 0;
    asm volatile("cp.async.ca.shared.global [%0], [%1], 16, %2;" :: "r"(d), "l"(gsrc), "r"(sz));
}

// ---------------- fp16 tensor-core GEMM, cp.async 3-stage + ldmatrix ---------
// C = rowscale(A@B) (+bias) (ELU). A:[M,K] fp16 lda. B: [K,N] (or [N,K] if TRANSB) fp16.
// Block 128x64, 128 thr, warp grid 2x2, warp tile 64x32. K%8==0 required (padded).
template <bool TRANSB, int ACT, bool OUTH, bool WRZ>
__global__ void __launch_bounds__(128)
hgemm_k(const __half* __restrict__ A, const __half* __restrict__ B,
        const float* __restrict__ bias, const float* __restrict__ rowscale,
        void* __restrict__ Cv, float* __restrict__ zout,
        int M, int N, int K, int lda, int ldb, int ldc,
        long sA, long sB, long sC, long sScale)
{
    extern __shared__ __half smh[];
    constexpr int BOFF = 128 * 40;

    A += (long)blockIdx.z * sA;
    B += (long)blockIdx.z * sB;
    const float* rs = rowscale ? rowscale + (long)blockIdx.z * sScale : nullptr;

    const int tid  = threadIdx.x;
    const int warp = tid >> 5, lane = tid & 31;
    const int g    = lane >> 2, tig = lane & 3;
    const int wm   = warp >> 1, wn = warp & 1;
    const int m0   = blockIdx.y * 128, n0 = blockIdx.x * 64;

    const unsigned smbase = (unsigned)__cvta_generic_to_shared(smh);
    // A ldmatrix lane offset (halves): row = wm*64 + (lane&15) (+mi*16), col = 8*(lane>>4) (+kb)
    const unsigned offA = (wm * 64 + (lane & 15)) * 40 + 8 * (lane >> 4);
    // B TRANSB lane offset: rows n = wn*32 + (lane&7) (+ni*8), col = kb + 8*((lane>>3)&1)
    const unsigned offBT = (wn * 32 + (lane & 7)) * 40 + 8 * ((lane >> 3) & 1);
    // B non-trans (trans-ldmatrix) offset: rows k = (lane&15) (+kb), col = wn*32 (+ni*8)
    const unsigned offBN = (lane & 15) * 72 + wn * 32;

    float acc[4][4][4];
#pragma unroll
    for (int i = 0; i < 4; ++i)
#pragma unroll
        for (int j = 0; j < 4; ++j)
#pragma unroll
            for (int l = 0; l < 4; ++l) acc[i][j][l] = 0.f;

    const int kt = (K + 31) / 32;

    auto issue = [&](int t, int st) {
        int k0 = t * 32;
        __half* As = smh + st * SSTGH;
        __half* Bs = As + BOFF;
#pragma unroll
        for (int i = 0; i < 4; ++i) {          // A: 128 rows x 4 chunks(8h)
            int f = tid + i * 128;
            int row = f >> 2, ck = (f & 3) * 8;
            int gm = m0 + row, gk = k0 + ck;
            bool p = (gm < M) && (gk < K);
            cp16(&As[row * 40 + ck], p ? (A + (long)gm * lda + gk) : A, p);
        }
#pragma unroll
        for (int i = 0; i < 2; ++i) {
            int f = tid + i * 128;
            if (TRANSB) {                       // [n=64][k: 4 chunks]
                int nr = f >> 2, ck = (f & 3) * 8;
                int gn = n0 + nr, gk = k0 + ck;
                bool p = (gn < N) && (gk < K);
                cp16(&Bs[nr * 40 + ck], p ? (B + (long)gn * ldb + gk) : B, p);
            } else {                            // [k=32][n: 8 chunks]
                int row = f >> 3, cn = (f & 7) * 8;
                int gk = k0 + row, gn = n0 + cn;
                bool p = (gk < K) && (gn < N);
                cp16(&Bs[row * 72 + cn], p ? (B + (long)gk * ldb + gn) : B, p);
            }
        }
        asm volatile("cp.async.commit_group;");
    };

    issue(0, 0);
    if (kt > 1) issue(1, 1);

    for (int t = 0; t < kt; ++t) {
        asm volatile("cp.async.wait_group 1;");
        __syncthreads();
        if (t + 2 < kt) issue(t + 2, (t + 2) % 3);

        const unsigned stA = smbase + ((t % 3) * SSTGH) * 2;
        const unsigned stB = stA + BOFF * 2;
#pragma unroll
        for (int ks = 0; ks < 2; ++ks) {
            const int kb = ks * 16;
            unsigned af[4][4], bf[4][2];
#pragma unroll
            for (int mi = 0; mi < 4; ++mi)
                ldmx4(af[mi], stA + (offA + mi * 16 * 40 + kb) * 2);
#pragma unroll
            for (int ni = 0; ni < 4; ++ni) {
                if (TRANSB)
                    ldmx2(bf[ni], stB + (offBT + ni * 8 * 40 + kb) * 2);
                else
                    ldmx2t(bf[ni], stB + (offBN + ni * 8 + kb * 72) * 2);
            }
#pragma unroll
            for (int mi = 0; mi < 4; ++mi)
#pragma unroll
                for (int ni = 0; ni < 4; ++ni)
                    mma_f16(acc[mi][ni], af[mi], bf[ni]);
        }
        __syncthreads();
    }

#pragma unroll
    for (int mi = 0; mi < 4; ++mi) {
#pragma unroll
        for (int ni = 0; ni < 4; ++ni) {
            int r = m0 + wm * 64 + mi * 16 + g;
            int c = n0 + wn * 32 + ni * 8 + tig * 2;
            if (c >= N) continue;
            float bx = bias ? bias[c] : 0.f;
            float by = bias ? bias[c + 1] : 0.f;
#pragma unroll
            for (int h = 0; h < 2; ++h) {
                int rr = r + h * 8;
                if (rr >= M) continue;
                float sc = rs ? rs[rr] : 1.f;
                float vx = acc[mi][ni][h * 2 + 0] * sc + bx;
                float vy = acc[mi][ni][h * 2 + 1] * sc + by;
                if (ACT == 1) {
                    vx = (vx > 0.f) ? vx : expm1f(vx);
                    vy = (vy > 0.f) ? vy : expm1f(vy);
                }
                if (WRZ && c == Ff)
                    zout[(long)blockIdx.z * Ee + rr] = (vx > 0.f) ? 1.f / vx : 0.f;
                if (OUTH) {
                    __half* C = (__half*)Cv + (long)blockIdx.z * sC;
                    *(__half2*)(C + (long)rr * ldc + c) = __floats2half2_rn(vx, vy);
                } else {
                    float* C = (float*)Cv + (long)blockIdx.z * sC;
                    *(float2*)(C + (long)rr * ldc + c) = make_float2(vx, vy);
                }
            }
        }
    }
}

// ---------------- prep kernels -----------------------------------------------
__global__ void cvt_h4_k(const float* __restrict__ src, __half* __restrict__ dst, int n4)
{
    int i = blockIdx.x * 256 + threadIdx.x;
    if (i < n4) {
        float4 v = ((const float4*)src)[i];
        __half2* d = (__half2*)(dst + (long)i * 4);
        d[0] = __floats2half2_rn(v.x, v.y);
        d[1] = __floats2half2_rn(v.z, v.w);
    }
}

__global__ void cvt_half_k(const float* __restrict__ src, __half* __restrict__ dst, int n)
{
    int i = blockIdx.x * 256 + threadIdx.x;
    if (i < n) dst[i] = __float2half(src[i]);
}

__global__ void prep_cat_h(const float* __restrict__ L, const float* __restrict__ R,
                           __half* __restrict__ W, bool transL)
{
    int i = blockIdx.x * 256 + threadIdx.x;
    if (i >= 600 * FfP) return;
    int j = i / FfP, k = i % FfP;
    float v = 0.f;
    if (k < 300)
        v = (j < 300) ? (transL ? L[j * 300 + k] : L[k * 300 + j])
                      : R[k * 300 + (j - 300)];
    W[i] = __float2half(v);
}

__global__ void prep_t_h(const float* __restrict__ S, __half* __restrict__ W)
{
    int i = blockIdx.x * 256 + threadIdx.x;
    if (i >= 300 * FfP) return;
    int n = i / FfP, k = i % FfP;
    W[i] = __float2half((k < 300) ? S[k * 300 + n] : 0.f);
}

__global__ void prep_bias_k(const float* __restrict__ bp, float* __restrict__ b600)
{
    int i = blockIdx.x * 256 + threadIdx.x;
    if (i < 600) b600[i] = (i < 300) ? bp[i] : 0.f;
}

__global__ void gather_k(const int* __restrict__ idx,
                         const float* __restrict__ emb, __half* __restrict__ out)
{
    int row = blockIdx.x;
    int id = idx[row];
    id = max(0, min(id, Vv - 1));
    const float* src = emb + (long)id * Ff;
    __half2* dst = (__half2*)(out + (long)row * FfP);
    for (int c = threadIdx.x; c < FfP / 2; c += 128) {
        float x0 = (2 * c     < Ff) ? src[2 * c]     : 0.f;
        float x1 = (2 * c + 1 < Ff) ? src[2 * c + 1] : 0.f;
        dst[c] = __floats2half2_rn(x0, x1);
    }
}

__global__ void dot_scalar_k(const float* __restrict__ a, const float* __restrict__ b,
                             float* __restrict__ out, int K)
{
    __shared__ float sh[128];
    float s = 0.f;
    for (int c = threadIdx.x; c < K; c += 128) s += a[c] * b[c];
    sh[threadIdx.x] = s; __syncthreads();
    for (int o = 64; o > 0; o >>= 1) {
        if (threadIdx.x < o) sh[threadIdx.x] += sh[threadIdx.x + o];
        __syncthreads();
    }
    if (threadIdx.x == 0) *out = sh[0];
}

__device__ __forceinline__ float ldf(const float* p) { return *p; }
__device__ __forceinline__ float ldf(const __half* p) { return __half2float(*p); }

template <typename T>
__global__ void rowdots_k(const T* __restrict__ X, int ldx,
                          const float* __restrict__ v1, const float* __restrict__ v2,
                          const float* __restrict__ cptr, float alpha,
                          float* __restrict__ o1, float* __restrict__ o2, int K)
{
    int row = blockIdx.x;
    const T* x = X + (long)row * ldx;
    float s1 = 0.f, s2 = 0.f;
    for (int c = threadIdx.x; c < K; c += 128) {
        float xv = ldf(x + c);
        s1 += xv * v1[c];
        s2 += xv * v2[c];
    }
    __shared__ float r1[128], r2[128];
    r1[threadIdx.x] = s1; r2[threadIdx.x] = s2; __syncthreads();
    for (int o = 64; o > 0; o >>= 1) {
        if (threadIdx.x < o) { r1[threadIdx.x] += r1[threadIdx.x + o]; r2[threadIdx.x] += r2[threadIdx.x + o]; }
        __syncthreads();
    }
    if (threadIdx.x == 0) {
        float t = *cptr + r1[0];
        o1[row] = (t >= 0.f) ? t : alpha * t;
        o2[row] = r2[0];
    }
}

__global__ void rowdot_k(const float* __restrict__ X, const float* __restrict__ v,
                         float* __restrict__ o, int K)
{
    int row = blockIdx.x;
    const float* x = X + (long)row * K;
    float s = 0.f;
    for (int c = threadIdx.x; c < K; c += 128) s += x[c] * v[c];
    __shared__ float sh[128];
    sh[threadIdx.x] = s; __syncthreads();
    for (int o2 = 64; o2 > 0; o2 >>= 1) {
        if (threadIdx.x < o2) sh[threadIdx.x] += sh[threadIdx.x + o2];
        __syncthreads();
    }
    if (threadIdx.x == 0) o[row] = sh[0];
}

__global__ void bmax2_k(const float* __restrict__ X, const float* __restrict__ Y,
                        float* __restrict__ ox, float* __restrict__ oy, int len)
{
    __shared__ float shx[256], shy[256];
    int b = blockIdx.x;
    const float* x = X + (long)b * len;
    const float* y = Y + (long)b * len;
    float mx = -3.0e38f, my = -3.0e38f;
    for (int i = threadIdx.x; i < len; i += 256) {
        mx = fmaxf(mx, x[i]);
        my = fmaxf(my, y[i]);
    }
    shx[threadIdx.x] = mx; shy[threadIdx.x] = my; __syncthreads();
    for (int o = 128; o > 0; o >>= 1) {
        if (threadIdx.x < o) {
            shx[threadIdx.x] = fmaxf(shx[threadIdx.x], shx[threadIdx.x + o]);
            shy[threadIdx.x] = fmaxf(shy[threadIdx.x], shy[threadIdx.x + o]);
        }
        __syncthreads();
    }
    if (threadIdx.x == 0) { ox[b] = shx[0]; oy[b] = shy[0]; }
}

__global__ void bmax_k(const float* __restrict__ X, float* __restrict__ out, int len)
{
    __shared__ float sh[256];
    int b = blockIdx.x;
    const float* x = X + (long)b * len;
    float m = -3.0e38f;
    for (int i = threadIdx.x; i < len; i += 256) m = fmaxf(m, x[i]);
    sh[threadIdx.x] = m; __syncthreads();
    for (int o = 128; o > 0; o >>= 1) {
        if (threadIdx.x < o) sh[threadIdx.x] = fmaxf(sh[threadIdx.x], sh[threadIdx.x + o]);
        __syncthreads();
    }
    if (threadIdx.x == 0) out[b] = sh[0];
}

__global__ void build_y_k(const __half* __restrict__ X, int ldx,
                          const float* __restrict__ s1, const float* __restrict__ s1max,
                          __half* __restrict__ y)
{
    int row = blockIdx.x;
    int b = row >> 10;
    float w = expf(s1[row] - s1max[b]);
    const __half* x = X + (long)row * ldx;
    __half* yy = y + (long)row * YW;
    for (int c = threadIdx.x; c < YW; c += 128) {
        float v = (c < Ff) ? w * __half2float(x[c]) : ((c == Ff) ? w : 0.f);
        yy[c] = __float2half(v);
    }
}

__global__ void attn_build_k(const float* __restrict__ HT, const float* __restrict__ sn,
                             const float* __restrict__ se, const float* __restrict__ snmax,
                             const float* __restrict__ semax, const float* __restrict__ invZe,
                             __half* __restrict__ u2, float* __restrict__ zpart, float alpha)
{
    __shared__ float t[32][33];
    int b  = blockIdx.z;
    int n0 = blockIdx.x * 32, e0 = blockIdx.y * 32;
    int tx = threadIdx.x, ty = threadIdx.y;   // (32,8)

    float sh = snmax[b] + semax[b];
    sh = (sh >= 0.f) ? sh : alpha * sh;

    const float* src = HT + (long)b * Ee * Nn;
    float snv = sn[(long)b * Nn + n0 + tx];
#pragma unroll
    for (int i = 0; i < 32; i += 8) {
        int e = e0 + ty + i;
        float sev = se[(long)b * Ee + e];
        float ht  = src[(long)e * Nn + n0 + tx];
        float v = snv + sev;
        v = (v >= 0.f) ? v : alpha * v;
        t[ty + i][tx] = (ht > 0.f) ? expf(v - sh) : 0.f;
    }
    __syncthreads();

    float iz = invZe[(long)b * Ee + e0 + tx];
    __half* dst = u2 + (long)b * Nn * Ee;
#pragma unroll
    for (int i = 0; i < 32; i += 8) {
        int n = n0 + ty + i;
        dst[(long)n * Ee + e0 + tx] = __float2half(t[tx][ty + i] * iz);
    }

    if (ty == 0) {
        float s = 0.f;
#pragma unroll
        for (int e = 0; e < 32; ++e) s += t[e][tx];
        zpart[((long)b * Nn + n0 + tx) * 16 + blockIdx.y] = s;
    }
}

__global__ void zsum_k(const float* __restrict__ zpart, float* __restrict__ invZn)
{
    int i = blockIdx.x * 256 + threadIdx.x;
    if (i < ROWS) {
        float s = 0.f;
#pragma unroll
        for (int j = 0; j < 16; ++j) s += zpart[(long)i * 16 + j];
        invZn[i] = (s > 0.f) ? 1.f / s : 0.f;
    }
}

__global__ void concat_k(const float* __restrict__ px4, const float* __restrict__ sem,
                         __half* __restrict__ comb)
{
    int row = blockIdx.x;
    __half* dst = comb + (long)row * 600;
    const float* p = px4 + (long)row * 600;
    const float* s = sem + (long)row * HH;
    for (int c = threadIdx.x; c < HH; c += 128) {
        dst[c]      = __float2half(p[c]);
        dst[HH + c] = __float2half(s[c]);
    }
}

__global__ void final_k(const float* __restrict__ hpre, const float* __restrict__ px4,
                        const float* __restrict__ sem, const float* __restrict__ ln_g,
                        const float* __restrict__ ln_b, const float* __restrict__ A2,
                        const float* __restrict__ b2, float* __restrict__ out)
{
    int row = blockIdx.x;
    int tid = threadIdx.x;
    __shared__ float hs[HH];
    __shared__ float red[128];
    const float* hp = hpre + (long)row * HH;

    float s = 0.f;
    for (int c = tid; c < HH; c += 128) {
        float t = tanhf(hp[c]);
        hs[c] = t;
        s += t;
    }
    red[tid] = s; __syncthreads();
    for (int o = 64; o > 0; o >>= 1) {
        if (tid < o) red[tid] += red[tid + o];
        __syncthreads();
    }
    float mean = red[0] / (float)HH;
    __syncthreads();

    float vs = 0.f;
    for (int c = tid; c < HH; c += 128) { float d = hs[c] - mean; vs += d * d; }
    red[tid] = vs; __syncthreads();
    for (int o = 64; o > 0; o >>= 1) {
        if (tid < o) red[tid] += red[tid + o];
        __syncthreads();
    }
    float rstd = rsqrtf(red[0] / (float)HH + 1e-5f);
    __syncthreads();

    float gdot = 0.f;
    for (int c = tid; c < HH; c += 128) {
        float hn = (hs[c] - mean) * rstd * ln_g[c] + ln_b[c];
        gdot += hn * A2[c];
    }
    red[tid] = gdot; __syncthreads();
    for (int o = 64; o > 0; o >>= 1) {
        if (tid < o) red[tid] += red[tid + o];
        __syncthreads();
    }
    float gate = 1.f / (1.f + expf(-(red[0] + b2[0])));
    __syncthreads();

    const float* p = px4 + (long)row * 600;
    const float* se = sem + (long)row * HH;
    float* o = out + (long)row * HH;
    for (int c = tid; c < HH; c += 128)
        o[c] = gate * se[c] + (1.f - gate) * p[c];
}

// ---------------- launcher ---------------------------------------------------
extern "C" void kernel_launch(void* const* d_in, const int* in_sizes, int n_in,
                              void* d_out, int out_size)
{
    const int*   inp  = (const int*)d_in[0];
    const float* HT   = (const float*)d_in[1];
    const float* emb  = (const float*)d_in[2];
    const float* Wp   = (const float*)d_in[3];
    const float* bp   = (const float*)d_in[4];
    const float* w2_1 = (const float*)d_in[5];
    const float* w3_1 = (const float*)d_in[6];
    const float* wc1  = (const float*)d_in[7];
    const float* a11  = (const float*)d_in[8];
    const float* a21  = (const float*)d_in[9];
    const float* W2t  = (const float*)d_in[10];
    const float* w2_2 = (const float*)d_in[11];
    const float* w3_2 = (const float*)d_in[12];
    const float* wc2  = (const float*)d_in[13];
    const float* a12  = (const float*)d_in[14];
    const float* a22  = (const float*)d_in[15];
    const float* A1   = (const float*)d_in[16];
    const float* b1   = (const float*)d_in[17];
    const float* ln_g = (const float*)d_in[18];
    const float* ln_b = (const float*)d_in[19];
    const float* A2   = (const float*)d_in[20];
    const float* b2   = (const float*)d_in[21];
    float* outp = (float*)d_out;

    static bool attr_done = false;
    if (!attr_done) {
        cudaFuncSetAttribute((const void*)hgemm_k<true, 0, false, false>,
                             cudaFuncAttributeMaxDynamicSharedMemorySize, SMEMB);
        cudaFuncSetAttribute((const void*)hgemm_k<false, 0, true, true>,
                             cudaFuncAttributeMaxDynamicSharedMemorySize, SMEMB);
        cudaFuncSetAttribute((const void*)hgemm_k<false, 1, true, false>,
                             cudaFuncAttributeMaxDynamicSharedMemorySize, SMEMB);
        cudaFuncSetAttribute((const void*)hgemm_k<true, 0, true, false>,
                             cudaFuncAttributeMaxDynamicSharedMemorySize, SMEMB);
        cudaFuncSetAttribute((const void*)hgemm_k<false, 0, false, false>,
                             cudaFuncAttributeMaxDynamicSharedMemorySize, SMEMB);
        attr_done = true;
    }

    __half *hidden_h, *HT_h, *xx_h, *y_h, *edge_h, *u2_h, *x1_h, *comb_h, *wt_h;
    float *px4, *s1, *sn, *se, *e4, *zpart, *invZe, *invZn, *sem, *hpre, *gc,
          *s1max, *snmax, *semax, *b600;
    cudaGetSymbolAddress((void**)&hidden_h, g_hidden_h);
    cudaGetSymbolAddress((void**)&HT_h,   g_HT_h);
    cudaGetSymbolAddress((void**)&px4,    g_px4);
    cudaGetSymbolAddress((void**)&xx_h,   g_xx_h);
    cudaGetSymbolAddress((void**)&s1,     g_s1);
    cudaGetSymbolAddress((void**)&sn,     g_sn);
    cudaGetSymbolAddress((void**)&se,     g_se);
    cudaGetSymbolAddress((void**)&y_h,    g_y_h);
    cudaGetSymbolAddress((void**)&edge_h, g_edge_h);
    cudaGetSymbolAddress((void**)&e4,     g_e4);
    cudaGetSymbolAddress((void**)&u2_h,   g_u2_h);
    cudaGetSymbolAddress((void**)&zpart,  g_zpart);
    cudaGetSymbolAddress((void**)&invZe,  g_invZe);
    cudaGetSymbolAddress((void**)&invZn,  g_invZn);
    cudaGetSymbolAddress((void**)&x1_h,   g_x1_h);
    cudaGetSymbolAddress((void**)&sem,    g_sem);
    cudaGetSymbolAddress((void**)&comb_h, g_comb_h);
    cudaGetSymbolAddress((void**)&hpre,   g_hpre);
    cudaGetSymbolAddress((void**)&gc,     g_c);
    cudaGetSymbolAddress((void**)&s1max,  g_s1max);
    cudaGetSymbolAddress((void**)&snmax,  g_snmax);
    cudaGetSymbolAddress((void**)&semax,  g_semax);
    cudaGetSymbolAddress((void**)&wt_h,   g_wt_h);
    cudaGetSymbolAddress((void**)&b600,   g_b600);

    __half* Wcat1h = wt_h;                     // 600*304 = 182400
    __half* Wcat2h = wt_h + 182400;            // 182400
    __half* w31h   = wt_h + 364800;            // 91200
    __half* w32h   = wt_h + 456000;            // 91200
    __half* A1h    = wt_h + 547200;            // 180000

    auto grid = [](int M, int N, int Z) {
        return dim3((N + 63) / 64, (M + 127) / 128, Z);
    };

    // ---- prep (idempotent) ----
    prep_cat_h<<<(600 * FfP + 255) / 256, 256>>>(Wp,   w2_1, Wcat1h, true);
    prep_cat_h<<<(600 * FfP + 255) / 256, 256>>>(w2_2, W2t,  Wcat2h, false);
    prep_t_h<<<(300 * FfP + 255) / 256, 256>>>(w3_1, w31h);
    prep_t_h<<<(300 * FfP + 255) / 256, 256>>>(w3_2, w32h);
    cvt_half_k<<<(180000 + 255) / 256, 256>>>(A1, A1h, 180000);
    prep_bias_k<<<3, 256>>>(bp, b600);
    cvt_h4_k<<<(Bb * Ee * Nn / 4 + 255) / 256, 256>>>(HT, HT_h, Bb * Ee * Nn / 4);
    dot_scalar_k<<<1, 128>>>(wc1, a11, gc + 0, Ff);
    dot_scalar_k<<<1, 128>>>(wc2, a12, gc + 1, HH);
    gather_k<<<ROWS, 128>>>(inp, emb, hidden_h);

    // ---- fused [proj | x4] = hidden @ Wcat1^T + b600 (fp32 out) ----
    hgemm_k<true, 0, false, false><<<grid(ROWS, 600, 1), 128, SMEMB>>>(
        hidden_h, Wcat1h, b600, nullptr, px4, nullptr,
        ROWS, 600, FfP, FfP, FfP, 600, 0, 0, 0, 0);

    // ================= layer 1 (alpha 0.1, ELU) ==============================
    rowdots_k<float><<<ROWS, 128>>>(px4 + 300, 600, a11 + Ff, a21, gc + 0, 0.1f, s1, sn, Ff);
    bmax2_k<<<Bb, 256>>>(s1, sn, s1max, snmax, Nn);
    build_y_k<<<ROWS, 128>>>(hidden_h, FfP, s1, s1max, y_h);
    hgemm_k<false, 0, true, true><<<grid(Ee, YW, Bb), 128, SMEMB>>>(
        HT_h, y_h, nullptr, nullptr, edge_h, invZe,
        Ee, YW, Nn, Nn, YW, YW, (long)Ee * Nn, (long)Nn * YW, (long)Ee * YW, 0);
    hgemm_k<true, 0, false, false><<<grid(EROWS, 300, 1), 128, SMEMB>>>(
        edge_h, w31h, nullptr, invZe, e4, nullptr,
        EROWS, 300, FfP, YW, FfP, 300, 0, 0, 0, 0);
    rowdot_k<<<EROWS, 128>>>(e4, a21 + Ff, se, Ff);
    bmax_k<<<Bb, 256>>>(se, semax, Ee);
    attn_build_k<<<dim3(Nn / 32, Ee / 32, Bb), dim3(32, 8)>>>(
        HT, sn, se, snmax, semax, invZe, u2_h, zpart, 0.1f);
    zsum_k<<<(ROWS + 255) / 256, 256>>>(zpart, invZn);
    hgemm_k<false, 1, true, false><<<grid(Nn, FfP, Bb), 128, SMEMB>>>(
        u2_h, edge_h, nullptr, invZn, x1_h, nullptr,
        Nn, FfP, Ee, Ee, YW, FfP, (long)Nn * Ee, (long)Ee * YW, (long)Nn * FfP, Nn);

    // ================= layer 2 (alpha 0.2, transfer) =========================
    hgemm_k<true, 0, true, false><<<grid(ROWS, 600, 1), 128, SMEMB>>>(
        x1_h, Wcat2h, nullptr, nullptr, xx_h, nullptr,
        ROWS, 600, FfP, FfP, FfP, 600, 0, 0, 0, 0);
    rowdots_k<__half><<<ROWS, 128>>>(xx_h, 600, a12 + HH, a22, gc + 1, 0.2f, s1, sn, HH);
    bmax2_k<<<Bb, 256>>>(s1, sn, s1max, snmax, Nn);
    build_y_k<<<ROWS, 128>>>(xx_h + 300, 600, s1, s1max, y_h);
    hgemm_k<false, 0, true, true><<<grid(Ee, YW, Bb), 128, SMEMB>>>(
        HT_h, y_h, nullptr, nullptr, edge_h, invZe,
        Ee, YW, Nn, Nn, YW, YW, (long)Ee * Nn, (long)Nn * YW, (long)Ee * YW, 0);
    hgemm_k<true, 0, false, false><<<grid(EROWS, 300, 1), 128, SMEMB>>>(
        edge_h, w32h, nullptr, invZe, e4, nullptr,
        EROWS, 300, FfP, YW, FfP, 300, 0, 0, 0, 0);
    rowdot_k<<<EROWS, 128>>>(e4, a22 + HH, se, HH);
    bmax_k<<<Bb, 256>>>(se, semax, Ee);
    attn_build_k<<<dim3(Nn / 32, Ee / 32, Bb), dim3(32, 8)>>>(
        HT, sn, se, snmax, semax, invZe, u2_h, zpart, 0.2f);
    zsum_k<<<(ROWS + 255) / 256, 256>>>(zpart, invZn);
    hgemm_k<false, 0, false, false><<<grid(Nn, 300, Bb), 128, SMEMB>>>(
        u2_h, edge_h, nullptr, invZn, sem, nullptr,
        Nn, 300, Ee, Ee, YW, 300, (long)Nn * Ee, (long)Ee * YW, (long)Nn * 300, Nn);

    // ================= head ==================================================
    concat_k<<<ROWS, 128>>>(px4, sem, comb_h);
    hgemm_k<true, 0, false, false><<<grid(ROWS, 300, 1), 128, SMEMB>>>(
        comb_h, A1h, b1, nullptr, hpre, nullptr,
        ROWS, 300, 600, 600, 600, 300, 0, 0, 0, 0);
    final_k<<<ROWS, 128>>>(hpre, px4, sem, ln_g, ln_b, A2, b2, outp);
}

// round 13
// speedup vs baseline: 1.7643x; 1.0456x over previous
#include <cuda_runtime.h>
#include <cuda_fp16.h>
#include <math.h>

#define Bb 32
#define Nn 1024
#define Ee 512
#define Ff 300
#define HH 300
#define Vv 50001

constexpr int ROWS  = Bb * Nn;   // 32768
constexpr int EROWS = Bb * Ee;   // 16384
constexpr int YW    = 304;       // padded row width (300 data + w/Z + pad)
constexpr int FfP   = 304;       // padded K for 300-dims
constexpr int SSTGH = 128 * 40 + 64 * 40;      // halves per stage (A + B)
constexpr int SMEMB = SSTGH * 3 * 2;           // 46080 B, 3 stages

// ---------------- scratch ----------------------------------------------------
__device__ __align__(16) __half g_hidden_h[ROWS * FfP];
__device__ __align__(16) __half g_HT_h   [Bb * Ee * Nn];
__device__ float g_px4   [ROWS * 600];
__device__ __align__(16) __half g_xx_h  [ROWS * 600];
__device__ float g_s1    [ROWS];
__device__ float g_sn    [ROWS];
__device__ float g_se    [EROWS];
__device__ __align__(16) __half g_y_h   [ROWS * YW];
__device__ __align__(16) __half g_edge_h[EROWS * YW];
__device__ float g_e4    [EROWS * Ff];
__device__ __align__(16) __half g_u2_h  [Bb * Nn * Ee];
__device__ float g_zpart [ROWS * 16];
__device__ float g_invZe [EROWS];
__device__ float g_invZn [ROWS];
__device__ __align__(16) __half g_x1_h  [ROWS * FfP];
__device__ float g_sem   [ROWS * HH];
__device__ __align__(16) __half g_comb_h[ROWS * 600];
__device__ float g_hpre  [ROWS * HH];
__device__ float g_c     [2];
__device__ __align__(16) __half g_wt_h  [730000];
__device__ float g_b600  [600];

// ---------------- helpers ----------------------------------------------------
__device__ __forceinline__ void mma_f16(float* d, const unsigned* a, const unsigned* b) {
    asm volatile(
        "mma.sync.aligned.m16n8k16.row.col.f32.f16.f16.f32 "
        "{%0,%1,%2,%3}, {%4,%5,%6,%7}, {%8,%9}, {%0,%1,%2,%3};"
        : "+f"(d[0]), "+f"(d[1]), "+f"(d[2]), "+f"(d[3])
        : "r"(a[0]), "r"(a[1]), "r"(a[2]), "r"(a[3]), "r"(b[0]), "r"(b[1]));
}

__device__ __forceinline__ void ldmx4(unsigned* r, unsigned addr) {
    asm volatile("ldmatrix.sync.aligned.m8n8.x4.shared.b16 {%0,%1,%2,%3}, [%4];"
                 : "=r"(r[0]), "=r"(r[1]), "=r"(r[2]), "=r"(r[3]) : "r"(addr));
}
__device__ __forceinline__ void ldmx2(unsigned* r, unsigned addr) {
    asm volatile("ldmatrix.sync.aligned.m8n8.x2.shared.b16 {%0,%1}, [%2];"
                 : "=r"(r[0]), "=r"(r[1]) : "r"(addr));
}
__device__ __forceinline__ void ldmx2t(unsigned* r, unsigned addr) {
    asm volatile("ldmatrix.sync.aligned.m8n8.x2.trans.shared.b16 {%0,%1}, [%2];"
                 : "=r"(r[0]), "=r"(r[1]) : "r"(addr));
}

__device__ __forceinline__ void cp16(void* smem_dst, const void* gsrc, bool pred) {
    unsigned d = (unsigned)__cvta_generic_to_shared(smem_dst);
    int sz = pred ? 16 : 0;
    asm volatile("cp.async.ca.shared.global [%0], [%1], 16, %2;" :: "r"(d), "l"(gsrc), "r"(sz));
}

// ---------------- fp16 tensor-core GEMM, cp.async 3-stage + ldmatrix ---------
// C = rowscale(A@B) (+bias) (ELU) (+fp16 copy of cols<hlim into hout, batch stride sH).
// A:[M,K] fp16 lda. B: [K,N] (or [N,K] if TRANSB) fp16. K%8==0 (padded).
// Block 128x64, 128 thr, warp grid 2x2, warp tile 64x32.
template <bool TRANSB, int ACT, bool OUTH, bool WRZ, bool HCOPY>
__global__ void __launch_bounds__(128)
hgemm_k(const __half* __restrict__ A, const __half* __restrict__ B,
        const float* __restrict__ bias, const float* __restrict__ rowscale,
        void* __restrict__ Cv, float* __restrict__ zout,
        __half* __restrict__ hout, int hldc, int hlim, long sH,
        int M, int N, int K, int lda, int ldb, int ldc,
        long sA, long sB, long sC, long sScale)
{
    extern __shared__ __half smh[];
    constexpr int BOFF = 128 * 40;

    A += (long)blockIdx.z * sA;
    B += (long)blockIdx.z * sB;
    if (HCOPY) hout += (long)blockIdx.z * sH;
    const float* rs = rowscale ? rowscale + (long)blockIdx.z * sScale : nullptr;

    const int tid  = threadIdx.x;
    const int warp = tid >> 5, lane = tid & 31;
    const int g    = lane >> 2, tig = lane & 3;
    const int wm   = warp >> 1, wn = warp & 1;
    const int m0   = blockIdx.y * 128, n0 = blockIdx.x * 64;

    const unsigned smbase = (unsigned)__cvta_generic_to_shared(smh);
    const unsigned offA  = (wm * 64 + (lane & 15)) * 40 + 8 * (lane >> 4);
    const unsigned offBT = (wn * 32 + (lane & 7)) * 40 + 8 * ((lane >> 3) & 1);
    const unsigned offBN = (lane & 15) * 72 + wn * 32;

    float acc[4][4][4];
#pragma unroll
    for (int i = 0; i < 4; ++i)
#pragma unroll
        for (int j = 0; j < 4; ++j)
#pragma unroll
            for (int l = 0; l < 4; ++l) acc[i][j][l] = 0.f;

    const int kt = (K + 31) / 32;

    auto issue = [&](int t, int st) {
        int k0 = t * 32;
        __half* As = smh + st * SSTGH;
        __half* Bs = As + BOFF;
#pragma unroll
        for (int i = 0; i < 4; ++i) {
            int f = tid + i * 128;
            int row = f >> 2, ck = (f & 3) * 8;
            int gm = m0 + row, gk = k0 + ck;
            bool p = (gm < M) && (gk < K);
            cp16(&As[row * 40 + ck], p ? (A + (long)gm * lda + gk) : A, p);
        }
#pragma unroll
        for (int i = 0; i < 2; ++i) {
            int f = tid + i * 128;
            if (TRANSB) {
                int nr = f >> 2, ck = (f & 3) * 8;
                int gn = n0 + nr, gk = k0 + ck;
                bool p = (gn < N) && (gk < K);
                cp16(&Bs[nr * 40 + ck], p ? (B + (long)gn * ldb + gk) : B, p);
            } else {
                int row = f >> 3, cn = (f & 7) * 8;
                int gk = k0 + row, gn = n0 + cn;
                bool p = (gk < K) && (gn < N);
                cp16(&Bs[row * 72 + cn], p ? (B + (long)gk * ldb + gn) : B, p);
            }
        }
        asm volatile("cp.async.commit_group;");
    };

    issue(0, 0);
    if (kt > 1) issue(1, 1);

    for (int t = 0; t < kt; ++t) {
        asm volatile("cp.async.wait_group 1;");
        __syncthreads();                 // also orders slot (t+2)%3 overwrite
        if (t + 2 < kt) issue(t + 2, (t + 2) % 3);

        const unsigned stA = smbase + ((t % 3) * SSTGH) * 2;
        const unsigned stB = stA + BOFF * 2;
#pragma unroll
        for (int ks = 0; ks < 2; ++ks) {
            const int kb = ks * 16;
            unsigned af[4][4], bf[4][2];
#pragma unroll
            for (int mi = 0; mi < 4; ++mi)
                ldmx4(af[mi], stA + (offA + mi * 16 * 40 + kb) * 2);
#pragma unroll
            for (int ni = 0; ni < 4; ++ni) {
                if (TRANSB)
                    ldmx2(bf[ni], stB + (offBT + ni * 8 * 40 + kb) * 2);
                else
                    ldmx2t(bf[ni], stB + (offBN + ni * 8 + kb * 72) * 2);
            }
#pragma unroll
            for (int mi = 0; mi < 4; ++mi)
#pragma unroll
                for (int ni = 0; ni < 4; ++ni)
                    mma_f16(acc[mi][ni], af[mi], bf[ni]);
        }
    }

#pragma unroll
    for (int mi = 0; mi < 4; ++mi) {
#pragma unroll
        for (int ni = 0; ni < 4; ++ni) {
            int r = m0 + wm * 64 + mi * 16 + g;
            int c = n0 + wn * 32 + ni * 8 + tig * 2;
            if (c >= N) continue;
            float bx = bias ? bias[c] : 0.f;
            float by = bias ? bias[c + 1] : 0.f;
#pragma unroll
            for (int h = 0; h < 2; ++h) {
                int rr = r + h * 8;
                if (rr >= M) continue;
                float sc = rs ? rs[rr] : 1.f;
                float vx = acc[mi][ni][h * 2 + 0] * sc + bx;
                float vy = acc[mi][ni][h * 2 + 1] * sc + by;
                if (ACT == 1) {
                    vx = (vx > 0.f) ? vx : expm1f(vx);
                    vy = (vy > 0.f) ? vy : expm1f(vy);
                }
                if (WRZ && c == Ff)
                    zout[(long)blockIdx.z * Ee + rr] = (vx > 0.f) ? 1.f / vx : 0.f;
                if (HCOPY && c < hlim)
                    *(__half2*)(hout + (long)rr * hldc + c) = __floats2half2_rn(vx, vy);
                if (OUTH) {
                    __half* C = (__half*)Cv + (long)blockIdx.z * sC;
                    *(__half2*)(C + (long)rr * ldc + c) = __floats2half2_rn(vx, vy);
                } else {
                    float* C = (float*)Cv + (long)blockIdx.z * sC;
                    *(float2*)(C + (long)rr * ldc + c) = make_float2(vx, vy);
                }
            }
        }
    }
}

// ---------------- prep kernels -----------------------------------------------
__global__ void cvt_h4_k(const float* __restrict__ src, __half* __restrict__ dst, int n4)
{
    int i = blockIdx.x * 256 + threadIdx.x;
    if (i < n4) {
        float4 v = ((const float4*)src)[i];
        __half2* d = (__half2*)(dst + (long)i * 4);
        d[0] = __floats2half2_rn(v.x, v.y);
        d[1] = __floats2half2_rn(v.z, v.w);
    }
}

__global__ void cvt_half_k(const float* __restrict__ src, __half* __restrict__ dst, int n)
{
    int i = blockIdx.x * 256 + threadIdx.x;
    if (i < n) dst[i] = __float2half(src[i]);
}

__global__ void prep_cat_h(const float* __restrict__ L, const float* __restrict__ R,
                           __half* __restrict__ W, bool transL)
{
    int i = blockIdx.x * 256 + threadIdx.x;
    if (i >= 600 * FfP) return;
    int j = i / FfP, k = i % FfP;
    float v = 0.f;
    if (k < 300)
        v = (j < 300) ? (transL ? L[j * 300 + k] : L[k * 300 + j])
                      : R[k * 300 + (j - 300)];
    W[i] = __float2half(v);
}

__global__ void prep_t_h(const float* __restrict__ S, __half* __restrict__ W)
{
    int i = blockIdx.x * 256 + threadIdx.x;
    if (i >= 300 * FfP) return;
    int n = i / FfP, k = i % FfP;
    W[i] = __float2half((k < 300) ? S[k * 300 + n] : 0.f);
}

__global__ void prep_bias_k(const float* __restrict__ bp, float* __restrict__ b600)
{
    int i = blockIdx.x * 256 + threadIdx.x;
    if (i < 600) b600[i] = (i < 300) ? bp[i] : 0.f;
}

__global__ void gather_k(const int* __restrict__ idx,
                         const float* __restrict__ emb, __half* __restrict__ out)
{
    int row = blockIdx.x;
    int id = idx[row];
    id = max(0, min(id, Vv - 1));
    const float* src = emb + (long)id * Ff;
    __half2* dst = (__half2*)(out + (long)row * FfP);
    for (int c = threadIdx.x; c < FfP / 2; c += 128) {
        float x0 = (2 * c     < Ff) ? src[2 * c]     : 0.f;
        float x1 = (2 * c + 1 < Ff) ? src[2 * c + 1] : 0.f;
        dst[c] = __floats2half2_rn(x0, x1);
    }
}

__global__ void dot_scalar_k(const float* __restrict__ a, const float* __restrict__ b,
                             float* __restrict__ out, int K)
{
    __shared__ float sh[128];
    float s = 0.f;
    for (int c = threadIdx.x; c < K; c += 128) s += a[c] * b[c];
    sh[threadIdx.x] = s; __syncthreads();
    for (int o = 64; o > 0; o >>= 1) {
        if (threadIdx.x < o) sh[threadIdx.x] += sh[threadIdx.x + o];
        __syncthreads();
    }
    if (threadIdx.x == 0) *out = sh[0];
}

__device__ __forceinline__ float ldf(const float* p) { return *p; }
__device__ __forceinline__ float ldf(const __half* p) { return __half2float(*p); }

template <typename T>
__global__ void rowdots_k(const T* __restrict__ X, int ldx,
                          const float* __restrict__ v1, const float* __restrict__ v2,
                          const float* __restrict__ cptr, float alpha,
                          float* __restrict__ o1, float* __restrict__ o2, int K)
{
    int row = blockIdx.x;
    const T* x = X + (long)row * ldx;
    float s1 = 0.f, s2 = 0.f;
    for (int c = threadIdx.x; c < K; c += 128) {
        float xv = ldf(x + c);
        s1 += xv * v1[c];
        s2 += xv * v2[c];
    }
    __shared__ float r1[128], r2[128];
    r1[threadIdx.x] = s1; r2[threadIdx.x] = s2; __syncthreads();
    for (int o = 64; o > 0; o >>= 1) {
        if (threadIdx.x < o) { r1[threadIdx.x] += r1[threadIdx.x + o]; r2[threadIdx.x] += r2[threadIdx.x + o]; }
        __syncthreads();
    }
    if (threadIdx.x == 0) {
        float t = *cptr + r1[0];
        o1[row] = (t >= 0.f) ? t : alpha * t;
        o2[row] = r2[0];
    }
}

__global__ void rowdot_k(const float* __restrict__ X, const float* __restrict__ v,
                         float* __restrict__ o, int K)
{
    int row = blockIdx.x;
    const float* x = X + (long)row * K;
    float s = 0.f;
    for (int c = threadIdx.x; c < K; c += 128) s += x[c] * v[c];
    __shared__ float sh[128];
    sh[threadIdx.x] = s; __syncthreads();
    for (int o2 = 64; o2 > 0; o2 >>= 1) {
        if (threadIdx.x < o2) sh[threadIdx.x] += sh[threadIdx.x + o2];
        __syncthreads();
    }
    if (threadIdx.x == 0) o[row] = sh[0];
}

// y = [exp(s1)*x | exp(s1)]  (no shift: softmax is shift-invariant, scores ~0.1)
__global__ void build_y_k(const __half* __restrict__ X, int ldx,
                          const float* __restrict__ s1, __half* __restrict__ y)
{
    int row = blockIdx.x;
    float w = expf(s1[row]);
    const __half* x = X + (long)row * ldx;
    __half* yy = y + (long)row * YW;
    for (int c = threadIdx.x; c < YW; c += 128) {
        float v = (c < Ff) ? w * __half2float(x[c]) : ((c == Ff) ? w : 0.f);
        yy[c] = __float2half(v);
    }
}

// u2[b,n,e] = mask * exp(leaky(sn+se)) * invZe; zpart = per-tile row sums (fp16 HT)
__global__ void attn_build_k(const __half* __restrict__ HTh, const float* __restrict__ sn,
                             const float* __restrict__ se, const float* __restrict__ invZe,
                             __half* __restrict__ u2, float* __restrict__ zpart, float alpha)
{
    __shared__ float t[32][33];
    int b  = blockIdx.z;
    int n0 = blockIdx.x * 32, e0 = blockIdx.y * 32;
    int tx = threadIdx.x, ty = threadIdx.y;   // (32,8)

    const __half* src = HTh + (long)b * Ee * Nn;
    float snv = sn[(long)b * Nn + n0 + tx];
#pragma unroll
    for (int i = 0; i < 32; i += 8) {
        int e = e0 + ty + i;
        float sev = se[(long)b * Ee + e];
        float ht  = __half2float(src[(long)e * Nn + n0 + tx]);
        float v = snv + sev;
        v = (v >= 0.f) ? v : alpha * v;
        t[ty + i][tx] = (ht > 0.f) ? expf(v) : 0.f;
    }
    __syncthreads();

    float iz = invZe[(long)b * Ee + e0 + tx];
    __half* dst = u2 + (long)b * Nn * Ee;
#pragma unroll
    for (int i = 0; i < 32; i += 8) {
        int n = n0 + ty + i;
        dst[(long)n * Ee + e0 + tx] = __float2half(t[tx][ty + i] * iz);
    }

    if (ty == 0) {
        float s = 0.f;
#pragma unroll
        for (int e = 0; e < 32; ++e) s += t[e][tx];
        zpart[((long)b * Nn + n0 + tx) * 16 + blockIdx.y] = s;
    }
}

__global__ void zsum_k(const float* __restrict__ zpart, float* __restrict__ invZn)
{
    int i = blockIdx.x * 256 + threadIdx.x;
    if (i < ROWS) {
        float s = 0.f;
#pragma unroll
        for (int j = 0; j < 16; ++j) s += zpart[(long)i * 16 + j];
        invZn[i] = (s > 0.f) ? 1.f / s : 0.f;
    }
}

__global__ void final_k(const float* __restrict__ hpre, const float* __restrict__ px4,
                        const float* __restrict__ sem, const float* __restrict__ ln_g,
                        const float* __restrict__ ln_b, const float* __restrict__ A2,
                        const float* __restrict__ b2, float* __restrict__ out)
{
    int row = blockIdx.x;
    int tid = threadIdx.x;
    __shared__ float hs[HH];
    __shared__ float red[128];
    const float* hp = hpre + (long)row * HH;

    float s = 0.f;
    for (int c = tid; c < HH; c += 128) {
        float t = tanhf(hp[c]);
        hs[c] = t;
        s += t;
    }
    red[tid] = s; __syncthreads();
    for (int o = 64; o > 0; o >>= 1) {
        if (tid < o) red[tid] += red[tid + o];
        __syncthreads();
    }
    float mean = red[0] / (float)HH;
    __syncthreads();

    float vs = 0.f;
    for (int c = tid; c < HH; c += 128) { float d = hs[c] - mean; vs += d * d; }
    red[tid] = vs; __syncthreads();
    for (int o = 64; o > 0; o >>= 1) {
        if (tid < o) red[tid] += red[tid + o];
        __syncthreads();
    }
    float rstd = rsqrtf(red[0] / (float)HH + 1e-5f);
    __syncthreads();

    float gdot = 0.f;
    for (int c = tid; c < HH; c += 128) {
        float hn = (hs[c] - mean) * rstd * ln_g[c] + ln_b[c];
        gdot += hn * A2[c];
    }
    red[tid] = gdot; __syncthreads();
    for (int o = 64; o > 0; o >>= 1) {
        if (tid < o) red[tid] += red[tid + o];
        __syncthreads();
    }
    float gate = 1.f / (1.f + expf(-(red[0] + b2[0])));
    __syncthreads();

    const float* p = px4 + (long)row * 600;
    const float* se = sem + (long)row * HH;
    float* o = out + (long)row * HH;
    for (int c = tid; c < HH; c += 128)
        o[c] = gate * se[c] + (1.f - gate) * p[c];
}

// ---------------- launcher ---------------------------------------------------
extern "C" void kernel_launch(void* const* d_in, const int* in_sizes, int n_in,
                              void* d_out, int out_size)
{
    const int*   inp  = (const int*)d_in[0];
    const float* HT   = (const float*)d_in[1];
    const float* emb  = (const float*)d_in[2];
    const float* Wp   = (const float*)d_in[3];
    const float* bp   = (const float*)d_in[4];
    const float* w2_1 = (const float*)d_in[5];
    const float* w3_1 = (const float*)d_in[6];
    const float* wc1  = (const float*)d_in[7];
    const float* a11  = (const float*)d_in[8];
    const float* a21  = (const float*)d_in[9];
    const float* W2t  = (const float*)d_in[10];
    const float* w2_2 = (const float*)d_in[11];
    const float* w3_2 = (const float*)d_in[12];
    const float* wc2  = (const float*)d_in[13];
    const float* a12  = (const float*)d_in[14];
    const float* a22  = (const float*)d_in[15];
    const float* A1   = (const float*)d_in[16];
    const float* b1   = (const float*)d_in[17];
    const float* ln_g = (const float*)d_in[18];
    const float* ln_b = (const float*)d_in[19];
    const float* A2   = (const float*)d_in[20];
    const float* b2   = (const float*)d_in[21];
    float* outp = (float*)d_out;

    static bool attr_done = false;
    if (!attr_done) {
        cudaFuncSetAttribute((const void*)hgemm_k<true, 0, false, false, true>,
                             cudaFuncAttributeMaxDynamicSharedMemorySize, SMEMB);
        cudaFuncSetAttribute((const void*)hgemm_k<false, 0, true, true, false>,
                             cudaFuncAttributeMaxDynamicSharedMemorySize, SMEMB);
        cudaFuncSetAttribute((const void*)hgemm_k<true, 0, false, false, false>,
                             cudaFuncAttributeMaxDynamicSharedMemorySize, SMEMB);
        cudaFuncSetAttribute((const void*)hgemm_k<false, 1, true, false, false>,
                             cudaFuncAttributeMaxDynamicSharedMemorySize, SMEMB);
        cudaFuncSetAttribute((const void*)hgemm_k<true, 0, true, false, false>,
                             cudaFuncAttributeMaxDynamicSharedMemorySize, SMEMB);
        cudaFuncSetAttribute((const void*)hgemm_k<false, 0, false, false, true>,
                             cudaFuncAttributeMaxDynamicSharedMemorySize, SMEMB);
        attr_done = true;
    }

    __half *hidden_h, *HT_h, *xx_h, *y_h, *edge_h, *u2_h, *x1_h, *comb_h, *wt_h;
    float *px4, *s1, *sn, *se, *e4, *zpart, *invZe, *invZn, *sem, *hpre, *gc, *b600;
    cudaGetSymbolAddress((void**)&hidden_h, g_hidden_h);
    cudaGetSymbolAddress((void**)&HT_h,   g_HT_h);
    cudaGetSymbolAddress((void**)&px4,    g_px4);
    cudaGetSymbolAddress((void**)&xx_h,   g_xx_h);
    cudaGetSymbolAddress((void**)&s1,     g_s1);
    cudaGetSymbolAddress((void**)&sn,     g_sn);
    cudaGetSymbolAddress((void**)&se,     g_se);
    cudaGetSymbolAddress((void**)&y_h,    g_y_h);
    cudaGetSymbolAddress((void**)&edge_h, g_edge_h);
    cudaGetSymbolAddress((void**)&e4,     g_e4);
    cudaGetSymbolAddress((void**)&u2_h,   g_u2_h);
    cudaGetSymbolAddress((void**)&zpart,  g_zpart);
    cudaGetSymbolAddress((void**)&invZe,  g_invZe);
    cudaGetSymbolAddress((void**)&invZn,  g_invZn);
    cudaGetSymbolAddress((void**)&x1_h,   g_x1_h);
    cudaGetSymbolAddress((void**)&sem,    g_sem);
    cudaGetSymbolAddress((void**)&comb_h, g_comb_h);
    cudaGetSymbolAddress((void**)&hpre,   g_hpre);
    cudaGetSymbolAddress((void**)&gc,     g_c);
    cudaGetSymbolAddress((void**)&wt_h,   g_wt_h);
    cudaGetSymbolAddress((void**)&b600,   g_b600);

    __half* Wcat1h = wt_h;                     // 182400
    __half* Wcat2h = wt_h + 182400;            // 182400
    __half* w31h   = wt_h + 364800;            // 91200
    __half* w32h   = wt_h + 456000;            // 91200
    __half* A1h    = wt_h + 547200;            // 180000

    auto grid = [](int M, int N, int Z) {
        return dim3((N + 63) / 64, (M + 127) / 128, Z);
    };

    // ---- prep (idempotent) ----
    prep_cat_h<<<(600 * FfP + 255) / 256, 256>>>(Wp,   w2_1, Wcat1h, true);
    prep_cat_h<<<(600 * FfP + 255) / 256, 256>>>(w2_2, W2t,  Wcat2h, false);
    prep_t_h<<<(300 * FfP + 255) / 256, 256>>>(w3_1, w31h);
    prep_t_h<<<(300 * FfP + 255) / 256, 256>>>(w3_2, w32h);
    cvt_half_k<<<(180000 + 255) / 256, 256>>>(A1, A1h, 180000);
    prep_bias_k<<<3, 256>>>(bp, b600);
    cvt_h4_k<<<(Bb * Ee * Nn / 4 + 255) / 256, 256>>>(HT, HT_h, Bb * Ee * Nn / 4);
    dot_scalar_k<<<1, 128>>>(wc1, a11, gc + 0, Ff);
    dot_scalar_k<<<1, 128>>>(wc2, a12, gc + 1, HH);
    gather_k<<<ROWS, 128>>>(inp, emb, hidden_h);

    // ---- fused [proj | x4] = hidden @ Wcat1^T + b600 (fp32 + proj->comb_h) ----
    hgemm_k<true, 0, false, false, true><<<grid(ROWS, 600, 1), 128, SMEMB>>>(
        hidden_h, Wcat1h, b600, nullptr, px4, nullptr, comb_h, 600, 300, 0,
        ROWS, 600, FfP, FfP, FfP, 600, 0, 0, 0, 0);

    // ================= layer 1 (alpha 0.1, ELU) ==============================
    rowdots_k<float><<<ROWS, 128>>>(px4 + 300, 600, a11 + Ff, a21, gc + 0, 0.1f, s1, sn, Ff);
    build_y_k<<<ROWS, 128>>>(hidden_h, FfP, s1, y_h);
    hgemm_k<false, 0, true, true, false><<<grid(Ee, YW, Bb), 128, SMEMB>>>(
        HT_h, y_h, nullptr, nullptr, edge_h, invZe, nullptr, 0, 0, 0,
        Ee, YW, Nn, Nn, YW, YW, (long)Ee * Nn, (long)Nn * YW, (long)Ee * YW, 0);
    hgemm_k<true, 0, false, false, false><<<grid(EROWS, 300, 1), 128, SMEMB>>>(
        edge_h, w31h, nullptr, invZe, e4, nullptr, nullptr, 0, 0, 0,
        EROWS, 300, FfP, YW, FfP, 300, 0, 0, 0, 0);
    rowdot_k<<<EROWS, 128>>>(e4, a21 + Ff, se, Ff);
    attn_build_k<<<dim3(Nn / 32, Ee / 32, Bb), dim3(32, 8)>>>(
        HT_h, sn, se, invZe, u2_h, zpart, 0.1f);
    zsum_k<<<(ROWS + 255) / 256, 256>>>(zpart, invZn);
    hgemm_k<false, 1, true, false, false><<<grid(Nn, FfP, Bb), 128, SMEMB>>>(
        u2_h, edge_h, nullptr, invZn, x1_h, nullptr, nullptr, 0, 0, 0,
        Nn, FfP, Ee, Ee, YW, FfP, (long)Nn * Ee, (long)Ee * YW, (long)Nn * FfP, Nn);

    // ================= layer 2 (alpha 0.2, transfer) =========================
    hgemm_k<true, 0, true, false, false><<<grid(ROWS, 600, 1), 128, SMEMB>>>(
        x1_h, Wcat2h, nullptr, nullptr, xx_h, nullptr, nullptr, 0, 0, 0,
        ROWS, 600, FfP, FfP, FfP, 600, 0, 0, 0, 0);
    rowdots_k<__half><<<ROWS, 128>>>(xx_h, 600, a12 + HH, a22, gc + 1, 0.2f, s1, sn, HH);
    build_y_k<<<ROWS, 128>>>(xx_h + 300, 600, s1, y_h);
    hgemm_k<false, 0, true, true, false><<<grid(Ee, YW, Bb), 128, SMEMB>>>(
        HT_h, y_h, nullptr, nullptr, edge_h, invZe, nullptr, 0, 0, 0,
        Ee, YW, Nn, Nn, YW, YW, (long)Ee * Nn, (long)Nn * YW, (long)Ee * YW, 0);
    hgemm_k<true, 0, false, false, false><<<grid(EROWS, 300, 1), 128, SMEMB>>>(
        edge_h, w32h, nullptr, invZe, e4, nullptr, nullptr, 0, 0, 0,
        EROWS, 300, FfP, YW, FfP, 300, 0, 0, 0, 0);
    rowdot_k<<<EROWS, 128>>>(e4, a22 + HH, se, HH);
    attn_build_k<<<dim3(Nn / 32, Ee / 32, Bb), dim3(32, 8)>>>(
        HT_h, sn, se, invZe, u2_h, zpart, 0.2f);
    zsum_k<<<(ROWS + 255) / 256, 256>>>(zpart, invZn);
    // sem (fp32) + fp16 copy into comb_h[:,300:600] (batch stride Nn*600)
    hgemm_k<false, 0, false, false, true><<<grid(Nn, 300, Bb), 128, SMEMB>>>(
        u2_h, edge_h, nullptr, invZn, sem, nullptr, comb_h + 300, 600, 300, (long)Nn * 600,
        Nn, 300, Ee, Ee, YW, 300, (long)Nn * Ee, (long)Ee * YW, (long)Nn * 300, Nn);

    // ================= head ==================================================
    hgemm_k<true, 0, false, false, false><<<grid(ROWS, 300, 1), 128, SMEMB>>>(
        comb_h, A1h, b1, nullptr, hpre, nullptr, nullptr, 0, 0, 0,
        ROWS, 300, 600, 600, 600, 300, 0, 0, 0, 0);
    final_k<<<ROWS, 128>>>(hpre, px4, sem, ln_g, ln_b, A2, b2, outp);
}